// round 1
// baseline (speedup 1.0000x reference)
#include <cuda_runtime.h>
#include <mma.h>
#include <cstdint>

using namespace nvcuda;

#define BB   4
#define CC   192
#define HH   56
#define WWD  56
#define HWX  3136
#define LTOK 12544     // B*H*W
#define DIN  384
#define DST  16
#define DTR  12

// ---------------- scratch (device globals; no allocation allowed) ----------
__device__ float g_tok  [(size_t)LTOK * CC];        // LN1 output tokens (M, C)
__device__ float g_xz   [(size_t)LTOK * 2 * DIN];   // in_proj out (M, 768)
__device__ float g_xmc  [(size_t)LTOK * DIN];       // conv1d+silu out (M, 384)
__device__ float g_bc   [(size_t)LTOK * 32];        // per token: B[0..15], C[16..31]
__device__ float g_delta[(size_t)LTOK * DIN];       // softplus(dt_proj) (M, 384)
__device__ float g_y    [(size_t)LTOK * DIN];       // scan output (M, 384)
__device__ float g_yp   [(size_t)LTOK * CC];        // out_proj out (M, 192)
__device__ float g_x1   [(size_t)BB * CC * HWX];
__device__ float g_x2   [(size_t)BB * CC * HWX];
__device__ float g_tok2 [(size_t)LTOK * CC];
__device__ float g_hid  [(size_t)LTOK * 4 * CC];    // mlp hidden (M, 768)
__device__ float g_m    [(size_t)LTOK * CC];        // mlp out (M, 192)

// ---------------- LayerNorm over C with NCHW->(M,C) transpose --------------
// in: (B, C, HW) ; out: (B*HW, C) row-major
__global__ void k_ln(const float* __restrict__ in, const float* __restrict__ g,
                     const float* __restrict__ bta, float* __restrict__ out) {
    __shared__ float sh[32 * 193];
    int b  = blockIdx.y;
    int l0 = blockIdx.x * 32;
    int tx = threadIdx.x & 31;       // token within tile
    int ty = threadIdx.x >> 5;       // 0..7
    const size_t base = (size_t)b * CC * HWX;
    for (int c = ty; c < CC; c += 8)
        sh[tx * 193 + c] = in[base + (size_t)c * HWX + l0 + tx];
    __syncthreads();
    int lane = tx;
    for (int tk = ty * 4; tk < ty * 4 + 4; tk++) {
        float s = 0.f, s2 = 0.f;
#pragma unroll
        for (int j = 0; j < 6; j++) {
            float v = sh[tk * 193 + lane + j * 32];
            s += v; s2 += v * v;
        }
#pragma unroll
        for (int o = 16; o; o >>= 1) {
            s  += __shfl_xor_sync(0xffffffffu, s, o);
            s2 += __shfl_xor_sync(0xffffffffu, s2, o);
        }
        float m  = s * (1.f / CC);
        float va = s2 * (1.f / CC) - m * m;
        float rs = rsqrtf(va + 1e-5f);
        size_t row = ((size_t)b * HWX + l0 + tk) * CC;
#pragma unroll
        for (int j = 0; j < 6; j++) {
            int c = lane + j * 32;
            out[row + c] = (sh[tk * 193 + c] - m) * rs * g[c] + bta[c];
        }
    }
}

// ---------------- tf32 WMMA GEMM: C[M,N] = A[M,K] * W[N,K]^T ---------------
// A row-major (M,K); W row-major (N,K) == B col-major (K,N). M%64==0, N%64==0, K%32==0.
__global__ void k_gemm(const float* __restrict__ A, const float* __restrict__ Bw,
                       float* __restrict__ C, int N, int K) {
    __shared__ float As[64][40];
    __shared__ float Bs[64][40];
    int tid = threadIdx.x;
    int wid = tid >> 5;
    int m0 = blockIdx.x * 64, n0 = blockIdx.y * 64;
    int wm = (wid >> 1) * 32, wn = (wid & 1) * 32;

    wmma::fragment<wmma::accumulator, 16, 16, 8, float> acc[2][2];
#pragma unroll
    for (int i = 0; i < 2; i++)
#pragma unroll
        for (int j = 0; j < 2; j++) wmma::fill_fragment(acc[i][j], 0.f);

    int lr = tid >> 3;            // 0..15
    int lc = (tid & 7) * 4;       // 0..28

    for (int k0 = 0; k0 < K; k0 += 32) {
#pragma unroll
        for (int s = 0; s < 4; s++) {
            float4 va = *(const float4*)&A [(size_t)(m0 + lr + 16 * s) * K + k0 + lc];
            *(float4*)&As[lr + 16 * s][lc] = va;
            float4 vb = *(const float4*)&Bw[(size_t)(n0 + lr + 16 * s) * K + k0 + lc];
            *(float4*)&Bs[lr + 16 * s][lc] = vb;
        }
        __syncthreads();
#pragma unroll
        for (int kk = 0; kk < 32; kk += 8) {
            wmma::fragment<wmma::matrix_a, 16, 16, 8, wmma::precision::tf32, wmma::row_major> af[2];
            wmma::fragment<wmma::matrix_b, 16, 16, 8, wmma::precision::tf32, wmma::col_major> bf[2];
#pragma unroll
            for (int i = 0; i < 2; i++) {
                wmma::load_matrix_sync(af[i], &As[wm + 16 * i][kk], 40);
#pragma unroll
                for (int e = 0; e < af[i].num_elements; e++)
                    af[i].x[e] = wmma::__float_to_tf32(af[i].x[e]);
            }
#pragma unroll
            for (int j = 0; j < 2; j++) {
                wmma::load_matrix_sync(bf[j], &Bs[wn + 16 * j][kk], 40);
#pragma unroll
                for (int e = 0; e < bf[j].num_elements; e++)
                    bf[j].x[e] = wmma::__float_to_tf32(bf[j].x[e]);
            }
#pragma unroll
            for (int i = 0; i < 2; i++)
#pragma unroll
                for (int j = 0; j < 2; j++)
                    wmma::mma_sync(acc[i][j], af[i], bf[j], acc[i][j]);
        }
        __syncthreads();
    }
#pragma unroll
    for (int i = 0; i < 2; i++)
#pragma unroll
        for (int j = 0; j < 2; j++)
            wmma::store_matrix_sync(&C[(size_t)(m0 + wm + 16 * i) * N + n0 + wn + 16 * j],
                                    acc[i][j], N, wmma::mem_row_major);
}

// ---------------- causal depthwise conv1d (k=3) + SiLU ---------------------
__global__ void k_conv1d(const float* __restrict__ cw, const float* __restrict__ cb) {
    size_t idx = (size_t)blockIdx.x * 256 + threadIdx.x;
    if (idx >= (size_t)LTOK * DIN) return;
    int d = (int)(idx % DIN);
    size_t row = idx / DIN;
    int l = (int)(row % HWX);
    float w0 = cw[d * 3 + 0], w1 = cw[d * 3 + 1], w2 = cw[d * 3 + 2];
    float a = cb[d];
    float v2 = g_xz[row * 2 * DIN + d];
    float v1 = (l >= 1) ? g_xz[(row - 1) * 2 * DIN + d] : 0.f;
    float v0 = (l >= 2) ? g_xz[(row - 2) * 2 * DIN + d] : 0.f;
    a += w0 * v0 + w1 * v1 + w2 * v2;
    g_xmc[idx] = a / (1.f + expf(-a));
}

// ---------------- x_proj (44 outs) + dt_proj + softplus per token ----------
__global__ void k_xdbl(const float* __restrict__ xw, const float* __restrict__ dtw,
                       const float* __restrict__ dtb) {
    int r = blockIdx.x;
    __shared__ float xs[DIN];
    __shared__ float dts[DTR];
    int tid = threadIdx.x;   // 128 threads
    for (int i = tid; i < DIN; i += 128) xs[i] = g_xmc[(size_t)r * DIN + i];
    __syncthreads();
    if (tid < 44) {
        float s = 0.f;
        const float* w = xw + (size_t)tid * DIN;
#pragma unroll 8
        for (int k = 0; k < DIN; k++) s += xs[k] * __ldg(&w[k]);
        if (tid < DTR)       dts[tid] = s;
        else if (tid < DTR + DST) g_bc[(size_t)r * 32 + (tid - DTR)] = s;
        else                 g_bc[(size_t)r * 32 + 16 + (tid - DTR - DST)] = s;
    }
    __syncthreads();
    for (int d = tid; d < DIN; d += 128) {
        float s = dtb[d];
        const float* w = dtw + (size_t)d * DTR;
#pragma unroll
        for (int k = 0; k < DTR; k++) s += dts[k] * __ldg(&w[k]);
        g_delta[(size_t)r * DIN + d] = (s > 20.f) ? s : log1pf(expf(s));
    }
}

// ---------------- selective scan: thread = (b, d, n) ------------------------
// warp covers 2 d-channels x 16 states; 16-lane shuffle reduce for y.
__global__ void k_scan(const float* __restrict__ A_log, const float* __restrict__ Dskip) {
    int blk = blockIdx.x;                 // 0..95 : b*24 + dblk
    int b = blk / 24, dblk = blk % 24;
    int warp = threadIdx.x >> 5;
    int lane = threadIdx.x & 31;
    int dl = lane >> 4, n = lane & 15;
    int d = dblk * 16 + warp * 2 + dl;

    float An  = -expf(A_log[d * DST + n]);
    float Dsk = Dskip[d];
    size_t tb = (size_t)b * HWX;
    const float* pd = g_delta + tb * DIN + d;
    const float* px = g_xmc   + tb * DIN + d;
    const float* pb = g_bc    + tb * 32  + n;
    const float* pz = g_xz    + tb * 2 * DIN + DIN + d;
    float*       py = g_y     + tb * DIN + d;

    float h = 0.f;
#pragma unroll 4
    for (int t = 0; t < HWX; t++) {
        float del = __ldg(pd);
        float xv  = __ldg(px);
        float Bv  = __ldg(pb);
        float Cv  = __ldg(pb + 16);
        float dA  = __expf(del * An);
        h = fmaf(dA, h, del * xv * Bv);
        float yv = h * Cv;
        yv += __shfl_down_sync(0xffffffffu, yv, 8, 16);
        yv += __shfl_down_sync(0xffffffffu, yv, 4, 16);
        yv += __shfl_down_sync(0xffffffffu, yv, 2, 16);
        yv += __shfl_down_sync(0xffffffffu, yv, 1, 16);
        if (n == 0) {
            float zv = __ldg(pz);
            float sz = zv / (1.f + __expf(-zv));
            *py = (yv + xv * Dsk) * sz;
        }
        pd += DIN; px += DIN; pb += 32; pz += 2 * DIN; py += DIN;
    }
}

// ---------------- x1 = x + transpose(yp) ------------------------------------
__global__ void k_addT(const float* __restrict__ x, float* __restrict__ x1) {
    __shared__ float t[32][33];
    int b = blockIdx.z, c0 = blockIdx.y * 32, l0 = blockIdx.x * 32;
    int tx = threadIdx.x, ty = threadIdx.y;
    t[ty][tx] = g_yp[((size_t)b * HWX + l0 + ty) * CC + c0 + tx];
    __syncthreads();
    size_t idx = ((size_t)b * CC + c0 + ty) * HWX + l0 + tx;
    x1[idx] = x[idx] + t[tx][ty];
}

// ---------------- dw 3x3 conv + BN + exact GELU + residual ------------------
__global__ void k_dw(const float* __restrict__ w, const float* __restrict__ bg,
                     const float* __restrict__ bb, const float* __restrict__ bm,
                     const float* __restrict__ bv) {
    size_t idx = (size_t)blockIdx.x * 256 + threadIdx.x;
    if (idx >= (size_t)BB * CC * HWX) return;
    int wc = (int)(idx % WWD);
    int hr = (int)((idx / WWD) % HH);
    int bc = (int)(idx / HWX);
    int c  = bc % CC;
    const float* p = g_x1 + (size_t)bc * HWX;
    float acc = 0.f;
#pragma unroll
    for (int ky = 0; ky < 3; ky++) {
        int hy = hr + ky - 1;
        if (hy < 0 || hy >= HH) continue;
#pragma unroll
        for (int kx = 0; kx < 3; kx++) {
            int wx = wc + kx - 1;
            if (wx < 0 || wx >= WWD) continue;
            acc += p[hy * WWD + wx] * __ldg(&w[c * 9 + ky * 3 + kx]);
        }
    }
    float bn = (acc - bm[c]) * rsqrtf(bv[c] + 1e-5f) * bg[c] + bb[c];
    float gl = 0.5f * bn * (1.f + erff(bn * 0.70710678118654752f));
    g_x2[idx] = g_x1[idx] + gl;
}

// ---------------- bias + exact GELU on mlp hidden ---------------------------
__global__ void k_biasgelu(const float* __restrict__ b1) {
    size_t idx = (size_t)blockIdx.x * 256 + threadIdx.x;
    if (idx >= (size_t)LTOK * 4 * CC) return;
    int nn = (int)(idx % (4 * CC));
    float v = g_hid[idx] + b1[nn];
    g_hid[idx] = 0.5f * v * (1.f + erff(v * 0.70710678118654752f));
}

// ---------------- out = x2 + transpose(m) + b2 ------------------------------
__global__ void k_final(const float* __restrict__ b2, float* __restrict__ out) {
    __shared__ float t[32][33];
    int b = blockIdx.z, c0 = blockIdx.y * 32, l0 = blockIdx.x * 32;
    int tx = threadIdx.x, ty = threadIdx.y;
    t[ty][tx] = g_m[((size_t)b * HWX + l0 + ty) * CC + c0 + tx];
    __syncthreads();
    size_t idx = ((size_t)b * CC + c0 + ty) * HWX + l0 + tx;
    out[idx] = g_x2[idx] + t[tx][ty] + b2[c0 + ty];
}

// ---------------------------------------------------------------------------
extern "C" void kernel_launch(void* const* d_in, const int* in_sizes, int n_in,
                              void* d_out, int out_size) {
    const float* x         = (const float*)d_in[0];
    const float* ln1_g     = (const float*)d_in[1];
    const float* ln1_b     = (const float*)d_in[2];
    const float* in_proj_w = (const float*)d_in[3];
    const float* conv1d_w  = (const float*)d_in[4];
    const float* conv1d_b  = (const float*)d_in[5];
    const float* x_proj_w  = (const float*)d_in[6];
    const float* dt_proj_w = (const float*)d_in[7];
    const float* dt_proj_b = (const float*)d_in[8];
    const float* A_log     = (const float*)d_in[9];
    const float* Dskip     = (const float*)d_in[10];
    const float* out_proj_w= (const float*)d_in[11];
    const float* dw_w      = (const float*)d_in[12];
    const float* bn_g      = (const float*)d_in[13];
    const float* bn_b      = (const float*)d_in[14];
    const float* bn_mean   = (const float*)d_in[15];
    const float* bn_var    = (const float*)d_in[16];
    const float* ln2_g     = (const float*)d_in[17];
    const float* ln2_b     = (const float*)d_in[18];
    const float* mlp_w1    = (const float*)d_in[19];
    const float* mlp_b1    = (const float*)d_in[20];
    const float* mlp_w2    = (const float*)d_in[21];
    const float* mlp_b2    = (const float*)d_in[22];
    float* out = (float*)d_out;

    float *p_tok, *p_tok2, *p_xz, *p_y, *p_yp, *p_hid, *p_m, *p_x1, *p_x2;
    cudaGetSymbolAddress((void**)&p_tok,  g_tok);
    cudaGetSymbolAddress((void**)&p_tok2, g_tok2);
    cudaGetSymbolAddress((void**)&p_xz,   g_xz);
    cudaGetSymbolAddress((void**)&p_y,    g_y);
    cudaGetSymbolAddress((void**)&p_yp,   g_yp);
    cudaGetSymbolAddress((void**)&p_hid,  g_hid);
    cudaGetSymbolAddress((void**)&p_m,    g_m);
    cudaGetSymbolAddress((void**)&p_x1,   g_x1);
    cudaGetSymbolAddress((void**)&p_x2,   g_x2);

    dim3 lnGrid(HWX / 32, BB);
    dim3 tGrid(HWX / 32, CC / 32, BB);
    dim3 tBlk(32, 32);

    // 1. LN1 + NCHW -> (M, C)
    k_ln<<<lnGrid, 256>>>(x, ln1_g, ln1_b, p_tok);
    // 2. in_proj: (M,192) x (768,192)^T
    k_gemm<<<dim3(LTOK / 64, 12), 128>>>(p_tok, in_proj_w, p_xz, 2 * DIN, CC);
    // 3. conv1d + silu
    k_conv1d<<<(LTOK * DIN + 255) / 256, 256>>>(conv1d_w, conv1d_b);
    // 4. x_proj + dt_proj + softplus
    k_xdbl<<<LTOK, 128>>>(x_proj_w, dt_proj_w, dt_proj_b);
    // 5. selective scan (+ Dskip + silu(z) gate fused)
    k_scan<<<BB * (DIN / 16), 256>>>(A_log, Dskip);
    // 6. out_proj: (M,384) x (192,384)^T
    k_gemm<<<dim3(LTOK / 64, 3), 128>>>(p_y, out_proj_w, p_yp, CC, DIN);
    // 7. x1 = x + y^T
    k_addT<<<tGrid, tBlk>>>(x, p_x1);
    // 8. dw conv + BN + gelu + residual -> x2
    k_dw<<<(BB * CC * HWX + 255) / 256, 256>>>(dw_w, bn_g, bn_b, bn_mean, bn_var);
    // 9. LN2
    k_ln<<<lnGrid, 256>>>(p_x2, ln2_g, ln2_b, p_tok2);
    // 10. mlp1
    k_gemm<<<dim3(LTOK / 64, 12), 128>>>(p_tok2, mlp_w1, p_hid, 4 * CC, CC);
    // 11. bias + gelu
    k_biasgelu<<<(LTOK * 4 * CC + 255) / 256, 256>>>(mlp_b1);
    // 12. mlp2
    k_gemm<<<dim3(LTOK / 64, 3), 128>>>(p_hid, mlp_w2, p_m, CC, 4 * CC);
    // 13. out = x2 + m^T + b2
    k_final<<<tGrid, tBlk>>>(mlp_b2, out);
}

// round 2
// speedup vs baseline: 5.1097x; 5.1097x over previous
#include <cuda_runtime.h>
#include <mma.h>
#include <cstdint>

using namespace nvcuda;

#define BB   4
#define CC   192
#define HH   56
#define WWD  56
#define HWX  3136
#define LTOK 12544     // B*H*W
#define DIN  384
#define DST  16
#define DTR  12
#define NCH  56        // scan chunks
#define CL   56        // chunk length (NCH*CL == HWX)

// ---------------- scratch (device globals; no allocation allowed) ----------
__device__ float g_tok  [(size_t)LTOK * CC];
__device__ float g_xz   [(size_t)LTOK * 2 * DIN];
__device__ float g_xmc  [(size_t)LTOK * DIN];
__device__ float g_xdbl [(size_t)LTOK * 64];        // dt[0:12], B[12:28], C[28:44]
__device__ float g_xw_pad[64 * DIN];
__device__ float g_delta[(size_t)LTOK * DIN];
__device__ float g_y    [(size_t)LTOK * DIN];
__device__ float g_yp   [(size_t)LTOK * CC];
__device__ float g_x1   [(size_t)BB * CC * HWX];
__device__ float g_x2   [(size_t)BB * CC * HWX];
__device__ float g_tok2 [(size_t)LTOK * CC];
__device__ float g_hid  [(size_t)LTOK * 4 * CC];
__device__ float g_m    [(size_t)LTOK * CC];
__device__ float g_cP   [(size_t)BB * DIN * DST * NCH];
__device__ float g_cS   [(size_t)BB * DIN * DST * NCH];
__device__ float g_h0   [(size_t)BB * DIN * DST * NCH];

// ---------------- LayerNorm over C with NCHW->(M,C) transpose --------------
__global__ void k_ln(const float* __restrict__ in, const float* __restrict__ g,
                     const float* __restrict__ bta, float* __restrict__ out) {
    __shared__ float sh[32 * 193];
    int b  = blockIdx.y;
    int l0 = blockIdx.x * 32;
    int tx = threadIdx.x & 31;
    int ty = threadIdx.x >> 5;
    const size_t base = (size_t)b * CC * HWX;
    for (int c = ty; c < CC; c += 8)
        sh[tx * 193 + c] = in[base + (size_t)c * HWX + l0 + tx];
    __syncthreads();
    int lane = tx;
    for (int tk = ty * 4; tk < ty * 4 + 4; tk++) {
        float s = 0.f, s2 = 0.f;
#pragma unroll
        for (int j = 0; j < 6; j++) {
            float v = sh[tk * 193 + lane + j * 32];
            s += v; s2 += v * v;
        }
#pragma unroll
        for (int o = 16; o; o >>= 1) {
            s  += __shfl_xor_sync(0xffffffffu, s, o);
            s2 += __shfl_xor_sync(0xffffffffu, s2, o);
        }
        float m  = s * (1.f / CC);
        float va = s2 * (1.f / CC) - m * m;
        float rs = rsqrtf(va + 1e-5f);
        size_t row = ((size_t)b * HWX + l0 + tk) * CC;
#pragma unroll
        for (int j = 0; j < 6; j++) {
            int c = lane + j * 32;
            out[row + c] = (sh[tk * 193 + c] - m) * rs * g[c] + bta[c];
        }
    }
}

// ---------------- tf32 WMMA GEMM: C[M,N] = A[M,K] * W[N,K]^T ---------------
__global__ void k_gemm(const float* __restrict__ A, const float* __restrict__ Bw,
                       float* __restrict__ C, int N, int K) {
    __shared__ float As[128][36];
    __shared__ float Bs[64][36];
    int tid = threadIdx.x;
    int wid = tid >> 5;
    int m0 = blockIdx.x * 128, n0 = blockIdx.y * 64;
    int wm = (wid >> 1) * 32, wn = (wid & 1) * 32;

    wmma::fragment<wmma::accumulator, 16, 16, 8, float> acc[2][2];
#pragma unroll
    for (int i = 0; i < 2; i++)
#pragma unroll
        for (int j = 0; j < 2; j++) wmma::fill_fragment(acc[i][j], 0.f);

    int lr = tid >> 3;
    int lc = (tid & 7) * 4;

    for (int k0 = 0; k0 < K; k0 += 32) {
#pragma unroll
        for (int s = 0; s < 4; s++) {
            float4 va = *(const float4*)&A[(size_t)(m0 + lr + 32 * s) * K + k0 + lc];
            *(float4*)&As[lr + 32 * s][lc] = va;
        }
#pragma unroll
        for (int s = 0; s < 2; s++) {
            float4 vb = *(const float4*)&Bw[(size_t)(n0 + lr + 32 * s) * K + k0 + lc];
            *(float4*)&Bs[lr + 32 * s][lc] = vb;
        }
        __syncthreads();
#pragma unroll
        for (int kk = 0; kk < 32; kk += 8) {
            wmma::fragment<wmma::matrix_a, 16, 16, 8, wmma::precision::tf32, wmma::row_major> af[2];
            wmma::fragment<wmma::matrix_b, 16, 16, 8, wmma::precision::tf32, wmma::col_major> bf[2];
#pragma unroll
            for (int i = 0; i < 2; i++) {
                wmma::load_matrix_sync(af[i], &As[wm + 16 * i][kk], 36);
#pragma unroll
                for (int e = 0; e < af[i].num_elements; e++)
                    af[i].x[e] = wmma::__float_to_tf32(af[i].x[e]);
            }
#pragma unroll
            for (int j = 0; j < 2; j++) {
                wmma::load_matrix_sync(bf[j], &Bs[wn + 16 * j][kk], 36);
#pragma unroll
                for (int e = 0; e < bf[j].num_elements; e++)
                    bf[j].x[e] = wmma::__float_to_tf32(bf[j].x[e]);
            }
#pragma unroll
            for (int i = 0; i < 2; i++)
#pragma unroll
                for (int j = 0; j < 2; j++)
                    wmma::mma_sync(acc[i][j], af[i], bf[j], acc[i][j]);
        }
        __syncthreads();
    }
#pragma unroll
    for (int i = 0; i < 2; i++)
#pragma unroll
        for (int j = 0; j < 2; j++)
            wmma::store_matrix_sync(&C[(size_t)(m0 + wm + 16 * i) * N + n0 + wn + 16 * j],
                                    acc[i][j], N, wmma::mem_row_major);
}

// ---------------- causal depthwise conv1d (k=3) + SiLU ---------------------
__global__ void k_conv1d(const float* __restrict__ cw, const float* __restrict__ cb) {
    size_t idx = (size_t)blockIdx.x * 256 + threadIdx.x;
    if (idx >= (size_t)LTOK * DIN) return;
    int d = (int)(idx % DIN);
    size_t row = idx / DIN;
    int l = (int)(row % HWX);
    float w0 = cw[d * 3 + 0], w1 = cw[d * 3 + 1], w2 = cw[d * 3 + 2];
    float a = cb[d];
    float v2 = g_xz[row * 2 * DIN + d];
    float v1 = (l >= 1) ? g_xz[(row - 1) * 2 * DIN + d] : 0.f;
    float v0 = (l >= 2) ? g_xz[(row - 2) * 2 * DIN + d] : 0.f;
    a += w0 * v0 + w1 * v1 + w2 * v2;
    g_xmc[idx] = a / (1.f + expf(-a));
}

// ---------------- pad x_proj weights (44,384) -> (64,384) ------------------
__global__ void k_padw(const float* __restrict__ xw) {
    int i = blockIdx.x * 256 + threadIdx.x;
    if (i >= 64 * DIN) return;
    int r = i / DIN;
    g_xw_pad[i] = (r < 44) ? xw[i] : 0.f;
}

// ---------------- dt_proj + softplus ----------------------------------------
__global__ void k_dtproj(const float* __restrict__ dtw, const float* __restrict__ dtb) {
    __shared__ float wT[DTR * DIN];
    __shared__ float bsm[DIN];
    __shared__ float dts[8][DTR];
    int tid = threadIdx.x;
    for (int i = tid; i < DIN * DTR; i += 256)
        wT[(i % DTR) * DIN + (i / DTR)] = dtw[i];
    for (int i = tid; i < DIN; i += 256) bsm[i] = dtb[i];
    int r0 = blockIdx.x * 8;
    if (tid < 8 * DTR) {
        int t = tid / DTR, k = tid % DTR;
        dts[t][k] = g_xdbl[(size_t)(r0 + t) * 64 + k];
    }
    __syncthreads();
    int w = tid >> 5, lane = tid & 31;
    size_t row = (size_t)(r0 + w) * DIN;
    float dk[DTR];
#pragma unroll
    for (int k = 0; k < DTR; k++) dk[k] = dts[w][k];
    for (int d = lane; d < DIN; d += 32) {
        float s = bsm[d];
#pragma unroll
        for (int k = 0; k < DTR; k++) s = fmaf(dk[k], wT[k * DIN + d], s);
        g_delta[row + d] = (s > 20.f) ? s : log1pf(expf(s));
    }
}

// ---------------- chunked selective scan -------------------------------------
__global__ void k_scanA(const float* __restrict__ A_log) {
    int blk = blockIdx.x;
    int chunk = blk % NCH;
    int t0 = blk / NCH;
    int b = t0 / 24, dblk = t0 % 24;
    int warp = threadIdx.x >> 5, lane = threadIdx.x & 31;
    int dl = lane >> 4, n = lane & 15;
    int d = dblk * 16 + warp * 2 + dl;

    float An = -expf(A_log[d * DST + n]);
    size_t tb = (size_t)b * HWX + (size_t)chunk * CL;
    const float* pd = g_delta + tb * DIN + d;
    const float* px = g_xmc   + tb * DIN + d;
    const float* pb = g_xdbl  + tb * 64  + 12 + n;

    float P = 1.f, s = 0.f;
#pragma unroll 4
    for (int t = 0; t < CL; t++) {
        float del = __ldg(pd), xv = __ldg(px), Bv = __ldg(pb);
        float dA = __expf(del * An);
        P *= dA;
        s = fmaf(dA, s, del * xv * Bv);
        pd += DIN; px += DIN; pb += 64;
    }
    size_t idx = (((size_t)b * DIN + d) * DST + n) * NCH + chunk;
    g_cP[idx] = P;
    g_cS[idx] = s;
}

__global__ void k_scanB() {
    int i = blockIdx.x * 256 + threadIdx.x;
    if (i >= BB * DIN * DST) return;
    size_t base = (size_t)i * NCH;
    float h = 0.f;
    for (int c = 0; c < NCH; c++) {
        g_h0[base + c] = h;
        h = fmaf(g_cP[base + c], h, g_cS[base + c]);
    }
}

__global__ void k_scanC(const float* __restrict__ A_log, const float* __restrict__ Dskip) {
    int blk = blockIdx.x;
    int chunk = blk % NCH;
    int t0 = blk / NCH;
    int b = t0 / 24, dblk = t0 % 24;
    int warp = threadIdx.x >> 5, lane = threadIdx.x & 31;
    int dl = lane >> 4, n = lane & 15;
    int d = dblk * 16 + warp * 2 + dl;

    float An  = -expf(A_log[d * DST + n]);
    float Dsk = Dskip[d];
    size_t tb = (size_t)b * HWX + (size_t)chunk * CL;
    const float* pd = g_delta + tb * DIN + d;
    const float* px = g_xmc   + tb * DIN + d;
    const float* pb = g_xdbl  + tb * 64  + 12 + n;
    const float* pz = g_xz    + tb * 2 * DIN + DIN + d;
    float*       py = g_y     + tb * DIN + d;

    size_t idx = (((size_t)b * DIN + d) * DST + n) * NCH + chunk;
    float h = g_h0[idx];
#pragma unroll 4
    for (int t = 0; t < CL; t++) {
        float del = __ldg(pd);
        float xv  = __ldg(px);
        float Bv  = __ldg(pb);
        float Cv  = __ldg(pb + 16);
        float dA  = __expf(del * An);
        h = fmaf(dA, h, del * xv * Bv);
        float yv = h * Cv;
        yv += __shfl_down_sync(0xffffffffu, yv, 8, 16);
        yv += __shfl_down_sync(0xffffffffu, yv, 4, 16);
        yv += __shfl_down_sync(0xffffffffu, yv, 2, 16);
        yv += __shfl_down_sync(0xffffffffu, yv, 1, 16);
        if (n == 0) {
            float zv = __ldg(pz);
            float sz = zv / (1.f + __expf(-zv));
            *py = (yv + xv * Dsk) * sz;
        }
        pd += DIN; px += DIN; pb += 64; pz += 2 * DIN; py += DIN;
    }
}

// ---------------- x1 = x + transpose(yp) ------------------------------------
__global__ void k_addT(const float* __restrict__ x, float* __restrict__ x1) {
    __shared__ float t[32][33];
    int b = blockIdx.z, c0 = blockIdx.y * 32, l0 = blockIdx.x * 32;
    int tx = threadIdx.x, ty = threadIdx.y;
    t[ty][tx] = g_yp[((size_t)b * HWX + l0 + ty) * CC + c0 + tx];
    __syncthreads();
    size_t idx = ((size_t)b * CC + c0 + ty) * HWX + l0 + tx;
    x1[idx] = x[idx] + t[tx][ty];
}

// ---------------- dw 3x3 conv + BN + exact GELU + residual ------------------
__global__ void k_dw(const float* __restrict__ w, const float* __restrict__ bg,
                     const float* __restrict__ bb, const float* __restrict__ bm,
                     const float* __restrict__ bv) {
    size_t idx = (size_t)blockIdx.x * 256 + threadIdx.x;
    if (idx >= (size_t)BB * CC * HWX) return;
    int wc = (int)(idx % WWD);
    int hr = (int)((idx / WWD) % HH);
    int bc = (int)(idx / HWX);
    int c  = bc % CC;
    const float* p = g_x1 + (size_t)bc * HWX;
    float acc = 0.f;
#pragma unroll
    for (int ky = 0; ky < 3; ky++) {
        int hy = hr + ky - 1;
        if (hy < 0 || hy >= HH) continue;
#pragma unroll
        for (int kx = 0; kx < 3; kx++) {
            int wx = wc + kx - 1;
            if (wx < 0 || wx >= WWD) continue;
            acc += p[hy * WWD + wx] * __ldg(&w[c * 9 + ky * 3 + kx]);
        }
    }
    float bn = (acc - bm[c]) * rsqrtf(bv[c] + 1e-5f) * bg[c] + bb[c];
    float gl = 0.5f * bn * (1.f + erff(bn * 0.70710678118654752f));
    g_x2[idx] = g_x1[idx] + gl;
}

// ---------------- bias + exact GELU on mlp hidden ---------------------------
__global__ void k_biasgelu(const float* __restrict__ b1) {
    size_t idx = (size_t)blockIdx.x * 256 + threadIdx.x;
    if (idx >= (size_t)LTOK * 4 * CC) return;
    int nn = (int)(idx % (4 * CC));
    float v = g_hid[idx] + b1[nn];
    g_hid[idx] = 0.5f * v * (1.f + erff(v * 0.70710678118654752f));
}

// ---------------- out = x2 + transpose(m) + b2 ------------------------------
__global__ void k_final(const float* __restrict__ b2, float* __restrict__ out) {
    __shared__ float t[32][33];
    int b = blockIdx.z, c0 = blockIdx.y * 32, l0 = blockIdx.x * 32;
    int tx = threadIdx.x, ty = threadIdx.y;
    t[ty][tx] = g_m[((size_t)b * HWX + l0 + ty) * CC + c0 + tx];
    __syncthreads();
    size_t idx = ((size_t)b * CC + c0 + ty) * HWX + l0 + tx;
    out[idx] = g_x2[idx] + t[tx][ty] + b2[c0 + ty];
}

// ---------------------------------------------------------------------------
extern "C" void kernel_launch(void* const* d_in, const int* in_sizes, int n_in,
                              void* d_out, int out_size) {
    const float* x         = (const float*)d_in[0];
    const float* ln1_g     = (const float*)d_in[1];
    const float* ln1_b     = (const float*)d_in[2];
    const float* in_proj_w = (const float*)d_in[3];
    const float* conv1d_w  = (const float*)d_in[4];
    const float* conv1d_b  = (const float*)d_in[5];
    const float* x_proj_w  = (const float*)d_in[6];
    const float* dt_proj_w = (const float*)d_in[7];
    const float* dt_proj_b = (const float*)d_in[8];
    const float* A_log     = (const float*)d_in[9];
    const float* Dskip     = (const float*)d_in[10];
    const float* out_proj_w= (const float*)d_in[11];
    const float* dw_w      = (const float*)d_in[12];
    const float* bn_g      = (const float*)d_in[13];
    const float* bn_b      = (const float*)d_in[14];
    const float* bn_mean   = (const float*)d_in[15];
    const float* bn_var    = (const float*)d_in[16];
    const float* ln2_g     = (const float*)d_in[17];
    const float* ln2_b     = (const float*)d_in[18];
    const float* mlp_w1    = (const float*)d_in[19];
    const float* mlp_b1    = (const float*)d_in[20];
    const float* mlp_w2    = (const float*)d_in[21];
    const float* mlp_b2    = (const float*)d_in[22];
    float* out = (float*)d_out;

    float *p_tok, *p_tok2, *p_xz, *p_y, *p_yp, *p_hid, *p_m, *p_x1, *p_x2, *p_xd, *p_xwp, *p_xmc;
    cudaGetSymbolAddress((void**)&p_tok,  g_tok);
    cudaGetSymbolAddress((void**)&p_tok2, g_tok2);
    cudaGetSymbolAddress((void**)&p_xz,   g_xz);
    cudaGetSymbolAddress((void**)&p_y,    g_y);
    cudaGetSymbolAddress((void**)&p_yp,   g_yp);
    cudaGetSymbolAddress((void**)&p_hid,  g_hid);
    cudaGetSymbolAddress((void**)&p_m,    g_m);
    cudaGetSymbolAddress((void**)&p_x1,   g_x1);
    cudaGetSymbolAddress((void**)&p_x2,   g_x2);
    cudaGetSymbolAddress((void**)&p_xd,   g_xdbl);
    cudaGetSymbolAddress((void**)&p_xwp,  g_xw_pad);
    cudaGetSymbolAddress((void**)&p_xmc,  g_xmc);

    dim3 lnGrid(HWX / 32, BB);
    dim3 tGrid(HWX / 32, CC / 32, BB);
    dim3 tBlk(32, 32);

    k_ln<<<lnGrid, 256>>>(x, ln1_g, ln1_b, p_tok);
    k_gemm<<<dim3(LTOK / 128, 12), 256>>>(p_tok, in_proj_w, p_xz, 2 * DIN, CC);
    k_conv1d<<<(LTOK * DIN + 255) / 256, 256>>>(conv1d_w, conv1d_b);
    k_padw<<<(64 * DIN + 255) / 256, 256>>>(x_proj_w);
    k_gemm<<<dim3(LTOK / 128, 1), 256>>>(p_xmc, p_xwp, p_xd, 64, DIN);
    k_dtproj<<<LTOK / 8, 256>>>(dt_proj_w, dt_proj_b);
    k_scanA<<<BB * 24 * NCH, 256>>>(A_log);
    k_scanB<<<(BB * DIN * DST + 255) / 256, 256>>>();
    k_scanC<<<BB * 24 * NCH, 256>>>(A_log, Dskip);
    k_gemm<<<dim3(LTOK / 128, 3), 256>>>(p_y, out_proj_w, p_yp, CC, DIN);
    k_addT<<<tGrid, tBlk>>>(x, p_x1);
    k_dw<<<(BB * CC * HWX + 255) / 256, 256>>>(dw_w, bn_g, bn_b, bn_mean, bn_var);
    k_ln<<<lnGrid, 256>>>(p_x2, ln2_g, ln2_b, p_tok2);
    k_gemm<<<dim3(LTOK / 128, 12), 256>>>(p_tok2, mlp_w1, p_hid, 4 * CC, CC);
    k_biasgelu<<<(LTOK * 4 * CC + 255) / 256, 256>>>(mlp_b1);
    k_gemm<<<dim3(LTOK / 128, 3), 256>>>(p_hid, mlp_w2, p_m, CC, 4 * CC);
    k_final<<<tGrid, tBlk>>>(mlp_b2, out);
}

// round 3
// speedup vs baseline: 5.1564x; 1.0091x over previous
#include <cuda_runtime.h>
#include <mma.h>
#include <cstdint>

using namespace nvcuda;

#define BB   4
#define CC   192
#define HH   56
#define WWD  56
#define HWX  3136
#define LTOK 12544     // B*H*W
#define DIN  384
#define DST  16
#define DTR  12
#define NCH  56        // scan chunks
#define CL   56        // chunk length (NCH*CL == HWX)

// ---------------- scratch (device globals; no allocation allowed) ----------
__device__ float g_tok  [(size_t)LTOK * CC];
__device__ float g_xz   [(size_t)LTOK * 2 * DIN];
__device__ float g_xmc  [(size_t)LTOK * DIN];
__device__ float g_xdbl [(size_t)LTOK * 64];        // dt[0:12], B[12:28], C[28:44]
__device__ float g_xw_pad[64 * DIN];
__device__ float g_delta[(size_t)LTOK * DIN];
__device__ float g_y    [(size_t)LTOK * DIN];
__device__ float g_yp   [(size_t)LTOK * CC];
__device__ float g_x1   [(size_t)BB * CC * HWX];
__device__ float g_x2   [(size_t)BB * CC * HWX];
__device__ float g_tok2 [(size_t)LTOK * CC];
__device__ float g_hid  [(size_t)LTOK * 4 * CC];
__device__ float g_m    [(size_t)LTOK * CC];
__device__ float g_cP   [(size_t)BB * DIN * DST * NCH];
__device__ float g_cS   [(size_t)BB * DIN * DST * NCH];
__device__ float g_h0   [(size_t)BB * DIN * DST * NCH];

// ---------------- cp.async helpers ------------------------------------------
__device__ __forceinline__ void cp_async16(void* sdst, const void* gsrc) {
    uint32_t s = (uint32_t)__cvta_generic_to_shared(sdst);
    asm volatile("cp.async.cg.shared.global [%0], [%1], 16;\n" :: "r"(s), "l"(gsrc) : "memory");
}
__device__ __forceinline__ void cp_commit() {
    asm volatile("cp.async.commit_group;\n" ::: "memory");
}
__device__ __forceinline__ void cp_wait0() {
    asm volatile("cp.async.wait_group 0;\n" ::: "memory");
}

// ---------------- LayerNorm over C with NCHW->(M,C) transpose --------------
__global__ void k_ln(const float* __restrict__ in, const float* __restrict__ g,
                     const float* __restrict__ bta, float* __restrict__ out) {
    __shared__ float sh[32 * 193];
    int b  = blockIdx.y;
    int l0 = blockIdx.x * 32;
    int tx = threadIdx.x & 31;
    int ty = threadIdx.x >> 5;
    const size_t base = (size_t)b * CC * HWX;
    for (int c = ty; c < CC; c += 8)
        sh[tx * 193 + c] = in[base + (size_t)c * HWX + l0 + tx];
    __syncthreads();
    int lane = tx;
    for (int tk = ty * 4; tk < ty * 4 + 4; tk++) {
        float s = 0.f, s2 = 0.f;
#pragma unroll
        for (int j = 0; j < 6; j++) {
            float v = sh[tk * 193 + lane + j * 32];
            s += v; s2 += v * v;
        }
#pragma unroll
        for (int o = 16; o; o >>= 1) {
            s  += __shfl_xor_sync(0xffffffffu, s, o);
            s2 += __shfl_xor_sync(0xffffffffu, s2, o);
        }
        float m  = s * (1.f / CC);
        float va = s2 * (1.f / CC) - m * m;
        float rs = rsqrtf(va + 1e-5f);
        size_t row = ((size_t)b * HWX + l0 + tk) * CC;
#pragma unroll
        for (int j = 0; j < 6; j++) {
            int c = lane + j * 32;
            out[row + c] = (sh[tk * 193 + c] - m) * rs * g[c] + bta[c];
        }
    }
}

// ---------------- pipelined tf32 WMMA GEMM ----------------------------------
// C[M,N] = A[M,K] * W[N,K]^T (+ optional bias+GELU epilogue)
// Tile: 128 x BN x 32, double-buffered cp.async. 256 threads.
// M%128==0, N%BN==0, K%32==0.
template<int BN, bool DOGELU>
__global__ void k_gemm2(const float* __restrict__ A, const float* __restrict__ Bw,
                        const float* __restrict__ bias, float* __restrict__ C,
                        int N, int K) {
    extern __shared__ float sm[];
    float* sA = sm;                       // [2][128][36]
    float* sB = sm + 2 * 128 * 36;        // [2][BN][36]
    constexpr int WN    = (BN == 128) ? 64 : 32;
    constexpr int NFRAG = WN / 16;
    constexpr int BROWS = BN / 32;        // B-tile row-batches per thread

    int tid = threadIdx.x;
    int wid = tid >> 5;
    int m0 = blockIdx.x * 128, n0 = blockIdx.y * BN;
    int wm = (wid >> 1) * 32, wn = (wid & 1) * WN;

    wmma::fragment<wmma::accumulator, 16, 16, 8, float> acc[2][NFRAG];
#pragma unroll
    for (int i = 0; i < 2; i++)
#pragma unroll
        for (int j = 0; j < NFRAG; j++) wmma::fill_fragment(acc[i][j], 0.f);

    int lr = tid >> 3;            // 0..31
    int lc = (tid & 7) * 4;       // 0,4,..,28

    const int T = K >> 5;         // K/32 steps

    // prologue: load tile 0 into buffer 0
    {
        const float* a0 = A + (size_t)(m0 + lr) * K + lc;
#pragma unroll
        for (int s = 0; s < 4; s++)
            cp_async16(&sA[(lr + 32 * s) * 36 + lc], a0 + (size_t)(32 * s) * K);
        const float* b0 = Bw + (size_t)(n0 + lr) * K + lc;
#pragma unroll
        for (int s = 0; s < BROWS; s++)
            cp_async16(&sB[(lr + 32 * s) * 36 + lc], b0 + (size_t)(32 * s) * K);
        cp_commit();
    }

    for (int it = 0; it < T; it++) {
        cp_wait0();
        __syncthreads();
        int buf = it & 1;
        if (it + 1 < T) {
            int nb = (it + 1) & 1;
            int k0 = (it + 1) << 5;
            const float* a0 = A + (size_t)(m0 + lr) * K + k0 + lc;
#pragma unroll
            for (int s = 0; s < 4; s++)
                cp_async16(&sA[nb * 128 * 36 + (lr + 32 * s) * 36 + lc], a0 + (size_t)(32 * s) * K);
            const float* b0 = Bw + (size_t)(n0 + lr) * K + k0 + lc;
#pragma unroll
            for (int s = 0; s < BROWS; s++)
                cp_async16(&sB[nb * BN * 36 + (lr + 32 * s) * 36 + lc], b0 + (size_t)(32 * s) * K);
            cp_commit();
        }
        const float* Ab = sA + buf * 128 * 36;
        const float* Bb = sB + buf * BN * 36;
#pragma unroll
        for (int kk = 0; kk < 32; kk += 8) {
            wmma::fragment<wmma::matrix_a, 16, 16, 8, wmma::precision::tf32, wmma::row_major> af[2];
            wmma::fragment<wmma::matrix_b, 16, 16, 8, wmma::precision::tf32, wmma::col_major> bf[NFRAG];
#pragma unroll
            for (int i = 0; i < 2; i++) {
                wmma::load_matrix_sync(af[i], Ab + (wm + 16 * i) * 36 + kk, 36);
#pragma unroll
                for (int e = 0; e < af[i].num_elements; e++)
                    af[i].x[e] = wmma::__float_to_tf32(af[i].x[e]);
            }
#pragma unroll
            for (int j = 0; j < NFRAG; j++) {
                wmma::load_matrix_sync(bf[j], Bb + (wn + 16 * j) * 36 + kk, 36);
#pragma unroll
                for (int e = 0; e < bf[j].num_elements; e++)
                    bf[j].x[e] = wmma::__float_to_tf32(bf[j].x[e]);
            }
#pragma unroll
            for (int i = 0; i < 2; i++)
#pragma unroll
                for (int j = 0; j < NFRAG; j++)
                    wmma::mma_sync(acc[i][j], af[i], bf[j], acc[i][j]);
        }
        __syncthreads();
    }

    if (!DOGELU) {
#pragma unroll
        for (int i = 0; i < 2; i++)
#pragma unroll
            for (int j = 0; j < NFRAG; j++)
                wmma::store_matrix_sync(&C[(size_t)(m0 + wm + 16 * i) * N + n0 + wn + 16 * j],
                                        acc[i][j], N, wmma::mem_row_major);
    } else {
        // stage to smem, apply bias+gelu, write coalesced
        constexpr int PAD = BN + 4;
        float* stage = sm;   // fits: 128*PAD*4 <= smem size
        __syncthreads();
#pragma unroll
        for (int i = 0; i < 2; i++)
#pragma unroll
            for (int j = 0; j < NFRAG; j++)
                wmma::store_matrix_sync(&stage[(wm + 16 * i) * PAD + wn + 16 * j],
                                        acc[i][j], PAD, wmma::mem_row_major);
        __syncthreads();
        constexpr int V = BN / 4;      // float4 per row
        for (int idx = tid; idx < 128 * V; idx += 256) {
            int row = idx / V;
            int col = (idx % V) * 4;
            float4 v = *(const float4*)&stage[row * PAD + col];
            float4 bo = *(const float4*)&bias[n0 + col];
            float r[4] = {v.x + bo.x, v.y + bo.y, v.z + bo.z, v.w + bo.w};
#pragma unroll
            for (int q = 0; q < 4; q++)
                r[q] = 0.5f * r[q] * (1.f + erff(r[q] * 0.70710678118654752f));
            *(float4*)&C[(size_t)(m0 + row) * N + n0 + col] = make_float4(r[0], r[1], r[2], r[3]);
        }
    }
}

// ---------------- causal depthwise conv1d (k=3) + SiLU ---------------------
__global__ void k_conv1d(const float* __restrict__ cw, const float* __restrict__ cb) {
    size_t idx = (size_t)blockIdx.x * 256 + threadIdx.x;
    if (idx >= (size_t)LTOK * DIN) return;
    int d = (int)(idx % DIN);
    size_t row = idx / DIN;
    int l = (int)(row % HWX);
    float w0 = cw[d * 3 + 0], w1 = cw[d * 3 + 1], w2 = cw[d * 3 + 2];
    float a = cb[d];
    float v2 = g_xz[row * 2 * DIN + d];
    float v1 = (l >= 1) ? g_xz[(row - 1) * 2 * DIN + d] : 0.f;
    float v0 = (l >= 2) ? g_xz[(row - 2) * 2 * DIN + d] : 0.f;
    a += w0 * v0 + w1 * v1 + w2 * v2;
    g_xmc[idx] = a / (1.f + expf(-a));
}

// ---------------- pad x_proj weights (44,384) -> (64,384) ------------------
__global__ void k_padw(const float* __restrict__ xw) {
    int i = blockIdx.x * 256 + threadIdx.x;
    if (i >= 64 * DIN) return;
    int r = i / DIN;
    g_xw_pad[i] = (r < 44) ? xw[i] : 0.f;
}

// ---------------- dt_proj + softplus ----------------------------------------
__global__ void k_dtproj(const float* __restrict__ dtw, const float* __restrict__ dtb) {
    __shared__ float wT[DTR * DIN];
    __shared__ float bsm[DIN];
    __shared__ float dts[8][DTR];
    int tid = threadIdx.x;
    for (int i = tid; i < DIN * DTR; i += 256)
        wT[(i % DTR) * DIN + (i / DTR)] = dtw[i];
    for (int i = tid; i < DIN; i += 256) bsm[i] = dtb[i];
    int r0 = blockIdx.x * 8;
    if (tid < 8 * DTR) {
        int t = tid / DTR, k = tid % DTR;
        dts[t][k] = g_xdbl[(size_t)(r0 + t) * 64 + k];
    }
    __syncthreads();
    int w = tid >> 5, lane = tid & 31;
    size_t row = (size_t)(r0 + w) * DIN;
    float dk[DTR];
#pragma unroll
    for (int k = 0; k < DTR; k++) dk[k] = dts[w][k];
    for (int d = lane; d < DIN; d += 32) {
        float s = bsm[d];
#pragma unroll
        for (int k = 0; k < DTR; k++) s = fmaf(dk[k], wT[k * DIN + d], s);
        g_delta[row + d] = (s > 20.f) ? s : log1pf(expf(s));
    }
}

// ---------------- chunked selective scan -------------------------------------
__global__ void k_scanA(const float* __restrict__ A_log) {
    int blk = blockIdx.x;
    int chunk = blk % NCH;
    int t0 = blk / NCH;
    int b = t0 / 24, dblk = t0 % 24;
    int warp = threadIdx.x >> 5, lane = threadIdx.x & 31;
    int dl = lane >> 4, n = lane & 15;
    int d = dblk * 16 + warp * 2 + dl;

    float An = -expf(A_log[d * DST + n]);
    size_t tb = (size_t)b * HWX + (size_t)chunk * CL;
    const float* pd = g_delta + tb * DIN + d;
    const float* px = g_xmc   + tb * DIN + d;
    const float* pb = g_xdbl  + tb * 64  + 12 + n;

    float P = 1.f, s = 0.f;
#pragma unroll 4
    for (int t = 0; t < CL; t++) {
        float del = __ldg(pd), xv = __ldg(px), Bv = __ldg(pb);
        float dA = __expf(del * An);
        P *= dA;
        s = fmaf(dA, s, del * xv * Bv);
        pd += DIN; px += DIN; pb += 64;
    }
    size_t idx = (((size_t)b * DIN + d) * DST + n) * NCH + chunk;
    g_cP[idx] = P;
    g_cS[idx] = s;
}

__global__ void k_scanB() {
    int i = blockIdx.x * 256 + threadIdx.x;
    if (i >= BB * DIN * DST) return;
    size_t base = (size_t)i * NCH;
    float h = 0.f;
    for (int c = 0; c < NCH; c++) {
        g_h0[base + c] = h;
        h = fmaf(g_cP[base + c], h, g_cS[base + c]);
    }
}

__global__ void k_scanC(const float* __restrict__ A_log, const float* __restrict__ Dskip) {
    int blk = blockIdx.x;
    int chunk = blk % NCH;
    int t0 = blk / NCH;
    int b = t0 / 24, dblk = t0 % 24;
    int warp = threadIdx.x >> 5, lane = threadIdx.x & 31;
    int dl = lane >> 4, n = lane & 15;
    int d = dblk * 16 + warp * 2 + dl;

    float An  = -expf(A_log[d * DST + n]);
    float Dsk = Dskip[d];
    size_t tb = (size_t)b * HWX + (size_t)chunk * CL;
    const float* pd = g_delta + tb * DIN + d;
    const float* px = g_xmc   + tb * DIN + d;
    const float* pb = g_xdbl  + tb * 64  + 12 + n;
    const float* pz = g_xz    + tb * 2 * DIN + DIN + d;
    float*       py = g_y     + tb * DIN + d;

    size_t idx = (((size_t)b * DIN + d) * DST + n) * NCH + chunk;
    float h = g_h0[idx];
#pragma unroll 4
    for (int t = 0; t < CL; t++) {
        float del = __ldg(pd);
        float xv  = __ldg(px);
        float Bv  = __ldg(pb);
        float Cv  = __ldg(pb + 16);
        float dA  = __expf(del * An);
        h = fmaf(dA, h, del * xv * Bv);
        float yv = h * Cv;
        yv += __shfl_down_sync(0xffffffffu, yv, 8, 16);
        yv += __shfl_down_sync(0xffffffffu, yv, 4, 16);
        yv += __shfl_down_sync(0xffffffffu, yv, 2, 16);
        yv += __shfl_down_sync(0xffffffffu, yv, 1, 16);
        if (n == 0) {
            float zv = __ldg(pz);
            float sz = zv / (1.f + __expf(-zv));
            *py = (yv + xv * Dsk) * sz;
        }
        pd += DIN; px += DIN; pb += 64; pz += 2 * DIN; py += DIN;
    }
}

// ---------------- x1 = x + transpose(yp) ------------------------------------
__global__ void k_addT(const float* __restrict__ x, float* __restrict__ x1) {
    __shared__ float t[32][33];
    int b = blockIdx.z, c0 = blockIdx.y * 32, l0 = blockIdx.x * 32;
    int tx = threadIdx.x, ty = threadIdx.y;
    t[ty][tx] = g_yp[((size_t)b * HWX + l0 + ty) * CC + c0 + tx];
    __syncthreads();
    size_t idx = ((size_t)b * CC + c0 + ty) * HWX + l0 + tx;
    x1[idx] = x[idx] + t[tx][ty];
}

// ---------------- dw 3x3 conv + BN + exact GELU + residual ------------------
__global__ void k_dw(const float* __restrict__ w, const float* __restrict__ bg,
                     const float* __restrict__ bb, const float* __restrict__ bm,
                     const float* __restrict__ bv) {
    size_t idx = (size_t)blockIdx.x * 256 + threadIdx.x;
    if (idx >= (size_t)BB * CC * HWX) return;
    int wc = (int)(idx % WWD);
    int hr = (int)((idx / WWD) % HH);
    int bc = (int)(idx / HWX);
    int c  = bc % CC;
    const float* p = g_x1 + (size_t)bc * HWX;
    float acc = 0.f;
#pragma unroll
    for (int ky = 0; ky < 3; ky++) {
        int hy = hr + ky - 1;
        if (hy < 0 || hy >= HH) continue;
#pragma unroll
        for (int kx = 0; kx < 3; kx++) {
            int wx = wc + kx - 1;
            if (wx < 0 || wx >= WWD) continue;
            acc += p[hy * WWD + wx] * __ldg(&w[c * 9 + ky * 3 + kx]);
        }
    }
    float bn = (acc - bm[c]) * rsqrtf(bv[c] + 1e-5f) * bg[c] + bb[c];
    float gl = 0.5f * bn * (1.f + erff(bn * 0.70710678118654752f));
    g_x2[idx] = g_x1[idx] + gl;
}

// ---------------- out = x2 + transpose(m) + b2 ------------------------------
__global__ void k_final(const float* __restrict__ b2, float* __restrict__ out) {
    __shared__ float t[32][33];
    int b = blockIdx.z, c0 = blockIdx.y * 32, l0 = blockIdx.x * 32;
    int tx = threadIdx.x, ty = threadIdx.y;
    t[ty][tx] = g_m[((size_t)b * HWX + l0 + ty) * CC + c0 + tx];
    __syncthreads();
    size_t idx = ((size_t)b * CC + c0 + ty) * HWX + l0 + tx;
    out[idx] = g_x2[idx] + t[tx][ty] + b2[c0 + ty];
}

// ---------------------------------------------------------------------------
extern "C" void kernel_launch(void* const* d_in, const int* in_sizes, int n_in,
                              void* d_out, int out_size) {
    const float* x         = (const float*)d_in[0];
    const float* ln1_g     = (const float*)d_in[1];
    const float* ln1_b     = (const float*)d_in[2];
    const float* in_proj_w = (const float*)d_in[3];
    const float* conv1d_w  = (const float*)d_in[4];
    const float* conv1d_b  = (const float*)d_in[5];
    const float* x_proj_w  = (const float*)d_in[6];
    const float* dt_proj_w = (const float*)d_in[7];
    const float* dt_proj_b = (const float*)d_in[8];
    const float* A_log     = (const float*)d_in[9];
    const float* Dskip     = (const float*)d_in[10];
    const float* out_proj_w= (const float*)d_in[11];
    const float* dw_w      = (const float*)d_in[12];
    const float* bn_g      = (const float*)d_in[13];
    const float* bn_b      = (const float*)d_in[14];
    const float* bn_mean   = (const float*)d_in[15];
    const float* bn_var    = (const float*)d_in[16];
    const float* ln2_g     = (const float*)d_in[17];
    const float* ln2_b     = (const float*)d_in[18];
    const float* mlp_w1    = (const float*)d_in[19];
    const float* mlp_b1    = (const float*)d_in[20];
    const float* mlp_w2    = (const float*)d_in[21];
    const float* mlp_b2    = (const float*)d_in[22];
    float* out = (float*)d_out;

    float *p_tok, *p_tok2, *p_xz, *p_y, *p_yp, *p_hid, *p_m, *p_x1, *p_x2, *p_xd, *p_xwp, *p_xmc;
    cudaGetSymbolAddress((void**)&p_tok,  g_tok);
    cudaGetSymbolAddress((void**)&p_tok2, g_tok2);
    cudaGetSymbolAddress((void**)&p_xz,   g_xz);
    cudaGetSymbolAddress((void**)&p_y,    g_y);
    cudaGetSymbolAddress((void**)&p_yp,   g_yp);
    cudaGetSymbolAddress((void**)&p_hid,  g_hid);
    cudaGetSymbolAddress((void**)&p_m,    g_m);
    cudaGetSymbolAddress((void**)&p_x1,   g_x1);
    cudaGetSymbolAddress((void**)&p_x2,   g_x2);
    cudaGetSymbolAddress((void**)&p_xd,   g_xdbl);
    cudaGetSymbolAddress((void**)&p_xwp,  g_xw_pad);
    cudaGetSymbolAddress((void**)&p_xmc,  g_xmc);

    // dynamic smem sizes for pipelined GEMM
    const int SM128 = (2 * 128 * 36 + 2 * 128 * 36) * 4;   // 73728
    const int SM64  = (2 * 128 * 36 + 2 * 64  * 36) * 4;   // 55296
    cudaFuncSetAttribute(k_gemm2<128, false>, cudaFuncAttributeMaxDynamicSharedMemorySize, SM128);
    cudaFuncSetAttribute(k_gemm2<128, true >, cudaFuncAttributeMaxDynamicSharedMemorySize, SM128);
    cudaFuncSetAttribute(k_gemm2<64,  false>, cudaFuncAttributeMaxDynamicSharedMemorySize, SM64);

    dim3 lnGrid(HWX / 32, BB);
    dim3 tGrid(HWX / 32, CC / 32, BB);
    dim3 tBlk(32, 32);

    // 1. LN1
    k_ln<<<lnGrid, 256>>>(x, ln1_g, ln1_b, p_tok);
    // 2. in_proj (M,192)->(M,768)
    k_gemm2<128, false><<<dim3(LTOK / 128, 6), 256, SM128>>>(p_tok, in_proj_w, nullptr, p_xz, 2 * DIN, CC);
    // 3. conv1d + silu
    k_conv1d<<<(LTOK * DIN + 255) / 256, 256>>>(conv1d_w, conv1d_b);
    // 4. x_proj padded GEMM (M,384)->(M,64)
    k_padw<<<(64 * DIN + 255) / 256, 256>>>(x_proj_w);
    k_gemm2<64, false><<<dim3(LTOK / 128, 1), 256, SM64>>>(p_xmc, p_xwp, nullptr, p_xd, 64, DIN);
    // 5. dt_proj + softplus
    k_dtproj<<<LTOK / 8, 256>>>(dt_proj_w, dt_proj_b);
    // 6. chunked selective scan
    k_scanA<<<BB * 24 * NCH, 256>>>(A_log);
    k_scanB<<<(BB * DIN * DST + 255) / 256, 256>>>();
    k_scanC<<<BB * 24 * NCH, 256>>>(A_log, Dskip);
    // 7. out_proj (M,384)->(M,192)
    k_gemm2<64, false><<<dim3(LTOK / 128, 3), 256, SM64>>>(p_y, out_proj_w, nullptr, p_yp, CC, DIN);
    // 8. x1 = x + y^T
    k_addT<<<tGrid, tBlk>>>(x, p_x1);
    // 9. dw conv + BN + gelu + residual
    k_dw<<<(BB * CC * HWX + 255) / 256, 256>>>(dw_w, bn_g, bn_b, bn_mean, bn_var);
    // 10. LN2
    k_ln<<<lnGrid, 256>>>(p_x2, ln2_g, ln2_b, p_tok2);
    // 11. mlp1 + fused bias + gelu
    k_gemm2<128, true><<<dim3(LTOK / 128, 6), 256, SM128>>>(p_tok2, mlp_w1, mlp_b1, p_hid, 4 * CC, CC);
    // 12. mlp2
    k_gemm2<64, false><<<dim3(LTOK / 128, 3), 256, SM64>>>(p_hid, mlp_w2, nullptr, p_m, CC, 4 * CC);
    // 13. out = x2 + m^T + b2
    k_final<<<tGrid, tBlk>>>(mlp_b2, out);
}

// round 4
// speedup vs baseline: 11.2711x; 2.1859x over previous
#include <cuda_runtime.h>
#include <cuda_bf16.h>
#include <mma.h>
#include <cstdint>

using namespace nvcuda;

#define BB   4
#define CC   192
#define HH   56
#define WWD  56
#define HWX  3136
#define LTOK 12544     // B*H*W
#define DIN  384
#define DST  16
#define DTR  12
#define NCH  56        // scan chunks
#define CL   56        // chunk length (NCH*CL == HWX)

// ---------------- scratch (device globals; no allocation allowed) ----------
__device__ __nv_bfloat16 g_tok_bf [(size_t)LTOK * CC];
__device__ float         g_xz     [(size_t)LTOK * 2 * DIN];
__device__ float         g_xmc    [(size_t)LTOK * DIN];
__device__ __nv_bfloat16 g_xmc_bf [(size_t)LTOK * DIN];
__device__ float         g_xdbl   [(size_t)LTOK * 64];   // dt[0:12], B[12:28], C[28:44]
__device__ __nv_bfloat16 g_xw_bf  [64 * DIN];
__device__ __nv_bfloat16 g_w_in   [2 * DIN * CC];
__device__ __nv_bfloat16 g_w_out  [CC * DIN];
__device__ __nv_bfloat16 g_w1     [4 * CC * CC];
__device__ __nv_bfloat16 g_w2     [CC * 4 * CC];
__device__ float         g_cw_t   [3 * DIN];              // transposed conv weights
__device__ float         g_delta  [(size_t)LTOK * DIN];
__device__ __nv_bfloat16 g_ybf    [(size_t)LTOK * DIN];
__device__ float         g_yp     [(size_t)LTOK * CC];
__device__ float         g_x1     [(size_t)BB * CC * HWX];
__device__ float         g_x2     [(size_t)BB * CC * HWX];
__device__ __nv_bfloat16 g_tok2_bf[(size_t)LTOK * CC];
__device__ __nv_bfloat16 g_hid_bf [(size_t)LTOK * 4 * CC];
__device__ float         g_m      [(size_t)LTOK * CC];
__device__ float         g_cP     [(size_t)BB * NCH * DST * DIN];
__device__ float         g_cS     [(size_t)BB * NCH * DST * DIN];
__device__ float         g_h0     [(size_t)BB * NCH * DST * DIN];

// ---------------- cp.async helpers ------------------------------------------
__device__ __forceinline__ void cp_async16(void* sdst, const void* gsrc) {
    uint32_t s = (uint32_t)__cvta_generic_to_shared(sdst);
    asm volatile("cp.async.cg.shared.global [%0], [%1], 16;\n" :: "r"(s), "l"(gsrc) : "memory");
}
__device__ __forceinline__ void cp_commit() {
    asm volatile("cp.async.commit_group;\n" ::: "memory");
}
__device__ __forceinline__ void cp_wait0() {
    asm volatile("cp.async.wait_group 0;\n" ::: "memory");
}

// ---------------- weight prep -------------------------------------------------
__global__ void k_padw(const float* __restrict__ xw) {
    int i = blockIdx.x * 256 + threadIdx.x;
    if (i >= 64 * DIN) return;
    int r = i / DIN;
    g_xw_bf[i] = __float2bfloat16((r < 44) ? xw[i] : 0.f);
}

__global__ void k_cvtw(const float* __restrict__ win, const float* __restrict__ wout,
                       const float* __restrict__ w1, const float* __restrict__ w2,
                       const float* __restrict__ cw) {
    const int N1 = 2 * DIN * CC, N2 = CC * DIN, N3 = 4 * CC * CC, N4 = CC * 4 * CC, N5 = 3 * DIN;
    int i = blockIdx.x * 256 + threadIdx.x;
    if (i < N1) { g_w_in[i] = __float2bfloat16(win[i]); return; }
    i -= N1;
    if (i < N2) { g_w_out[i] = __float2bfloat16(wout[i]); return; }
    i -= N2;
    if (i < N3) { g_w1[i] = __float2bfloat16(w1[i]); return; }
    i -= N3;
    if (i < N4) { g_w2[i] = __float2bfloat16(w2[i]); return; }
    i -= N4;
    if (i < N5) { int d = i % DIN, k = i / DIN; g_cw_t[k * DIN + d] = cw[d * 3 + k]; }
}

// ---------------- LayerNorm over C with NCHW->(M,C) transpose, bf16 out ------
__global__ void k_ln(const float* __restrict__ in, const float* __restrict__ g,
                     const float* __restrict__ bta, __nv_bfloat16* __restrict__ out) {
    __shared__ float sh[32 * 193];
    int b  = blockIdx.y;
    int l0 = blockIdx.x * 32;
    int tx = threadIdx.x & 31;
    int ty = threadIdx.x >> 5;
    const size_t base = (size_t)b * CC * HWX;
    for (int c = ty; c < CC; c += 8)
        sh[tx * 193 + c] = in[base + (size_t)c * HWX + l0 + tx];
    __syncthreads();
    int lane = tx;
    for (int tk = ty * 4; tk < ty * 4 + 4; tk++) {
        float s = 0.f, s2 = 0.f;
#pragma unroll
        for (int j = 0; j < 6; j++) {
            float v = sh[tk * 193 + lane + j * 32];
            s += v; s2 += v * v;
        }
#pragma unroll
        for (int o = 16; o; o >>= 1) {
            s  += __shfl_xor_sync(0xffffffffu, s, o);
            s2 += __shfl_xor_sync(0xffffffffu, s2, o);
        }
        float m  = s * (1.f / CC);
        float va = s2 * (1.f / CC) - m * m;
        float rs = rsqrtf(va + 1e-5f);
        size_t row = ((size_t)b * HWX + l0 + tk) * CC;
#pragma unroll
        for (int j = 0; j < 6; j++) {
            int c = lane + j * 32;
            out[row + c] = __float2bfloat16((sh[tk * 193 + c] - m) * rs * g[c] + bta[c]);
        }
    }
}

// ---------------- pipelined bf16 WMMA GEMM ------------------------------------
// C[M,N] = A[M,K] * W[N,K]^T. EPI 0: fp32 store. EPI 1: bias+GELU -> bf16 store.
// Tile 128 x BN x 32, double-buffered cp.async. 256 threads. smem rows padded to 40 bf16.
template<int BN, int EPI>
__global__ void k_gemmbf(const __nv_bfloat16* __restrict__ A,
                         const __nv_bfloat16* __restrict__ Bw,
                         const float* __restrict__ bias,
                         float* __restrict__ Cf, __nv_bfloat16* __restrict__ Cbf,
                         int N, int K) {
    extern __shared__ char smraw[];
    __nv_bfloat16* sA = (__nv_bfloat16*)smraw;           // [2][128][40]
    __nv_bfloat16* sB = sA + 2 * 128 * 40;               // [2][BN][40]
    constexpr int WN = (BN == 128) ? 64 : 32;
    constexpr int NF = WN / 16;
    int tid = threadIdx.x;
    int wid = tid >> 5;
    int m0 = blockIdx.x * 128, n0 = blockIdx.y * BN;
    int wm = (wid >> 1) * 32, wn = (wid & 1) * WN;

    wmma::fragment<wmma::accumulator, 16, 16, 16, float> acc[2][NF];
#pragma unroll
    for (int i = 0; i < 2; i++)
#pragma unroll
        for (int j = 0; j < NF; j++) wmma::fill_fragment(acc[i][j], 0.f);

    const int T = K >> 5;

    // tile loaders: each 16B chunk = 8 bf16; A tile = 512 chunks, B tile = BN*4 chunks
#define LOAD_A(buf, k0)                                                            \
    {                                                                              \
        _Pragma("unroll")                                                          \
        for (int s = 0; s < 2; s++) {                                              \
            int c = tid + 256 * s;                                                 \
            int r = c >> 2, co = (c & 3) * 8;                                      \
            cp_async16(sA + (buf) * 128 * 40 + r * 40 + co,                        \
                       A + (size_t)(m0 + r) * K + (k0) + co);                      \
        }                                                                          \
    }
#define LOAD_B(buf, k0)                                                            \
    {                                                                              \
        _Pragma("unroll")                                                          \
        for (int s = 0; s < BN / 64; s++) {                                        \
            int c = tid + 256 * s;                                                 \
            int r = c >> 2, co = (c & 3) * 8;                                      \
            cp_async16(sB + (buf) * BN * 40 + r * 40 + co,                         \
                       Bw + (size_t)(n0 + r) * K + (k0) + co);                     \
        }                                                                          \
    }

    LOAD_A(0, 0) LOAD_B(0, 0)
    cp_commit();

    for (int it = 0; it < T; it++) {
        cp_wait0();
        __syncthreads();
        int buf = it & 1;
        if (it + 1 < T) {
            LOAD_A(buf ^ 1, (it + 1) << 5)
            LOAD_B(buf ^ 1, (it + 1) << 5)
            cp_commit();
        }
        const __nv_bfloat16* Ab = sA + buf * 128 * 40;
        const __nv_bfloat16* Bb = sB + buf * BN * 40;
#pragma unroll
        for (int kk = 0; kk < 2; kk++) {
            wmma::fragment<wmma::matrix_a, 16, 16, 16, __nv_bfloat16, wmma::row_major> af[2];
            wmma::fragment<wmma::matrix_b, 16, 16, 16, __nv_bfloat16, wmma::col_major> bfm[NF];
#pragma unroll
            for (int i = 0; i < 2; i++)
                wmma::load_matrix_sync(af[i], Ab + (wm + 16 * i) * 40 + kk * 16, 40);
#pragma unroll
            for (int j = 0; j < NF; j++)
                wmma::load_matrix_sync(bfm[j], Bb + (wn + 16 * j) * 40 + kk * 16, 40);
#pragma unroll
            for (int i = 0; i < 2; i++)
#pragma unroll
                for (int j = 0; j < NF; j++)
                    wmma::mma_sync(acc[i][j], af[i], bfm[j], acc[i][j]);
        }
        __syncthreads();
    }
#undef LOAD_A
#undef LOAD_B

    if (EPI == 0) {
#pragma unroll
        for (int i = 0; i < 2; i++)
#pragma unroll
            for (int j = 0; j < NF; j++)
                wmma::store_matrix_sync(&Cf[(size_t)(m0 + wm + 16 * i) * N + n0 + wn + 16 * j],
                                        acc[i][j], N, wmma::mem_row_major);
    } else {
        constexpr int PAD = BN + 4;
        float* stage = (float*)smraw;
        __syncthreads();
#pragma unroll
        for (int i = 0; i < 2; i++)
#pragma unroll
            for (int j = 0; j < NF; j++)
                wmma::store_matrix_sync(&stage[(wm + 16 * i) * PAD + wn + 16 * j],
                                        acc[i][j], PAD, wmma::mem_row_major);
        __syncthreads();
        constexpr int V = BN / 4;
        for (int idx = tid; idx < 128 * V; idx += 256) {
            int row = idx / V;
            int col = (idx % V) * 4;
            float4 v = *(const float4*)&stage[row * PAD + col];
            float4 bo = *(const float4*)&bias[n0 + col];
            float r[4] = {v.x + bo.x, v.y + bo.y, v.z + bo.z, v.w + bo.w};
#pragma unroll
            for (int q = 0; q < 4; q++)
                r[q] = 0.5f * r[q] * (1.f + erff(r[q] * 0.70710678118654752f));
            size_t off = (size_t)(m0 + row) * N + n0 + col;
            __nv_bfloat162 p0 = __floats2bfloat162_rn(r[0], r[1]);
            __nv_bfloat162 p1 = __floats2bfloat162_rn(r[2], r[3]);
            *(__nv_bfloat162*)&Cbf[off]     = p0;
            *(__nv_bfloat162*)&Cbf[off + 2] = p1;
        }
    }
}

// ---------------- causal depthwise conv1d (k=3) + SiLU, x4 vectorized --------
__global__ void k_conv1d(const float* __restrict__ cb) {
    int idx = blockIdx.x * 256 + threadIdx.x;
    if (idx >= LTOK * (DIN / 4)) return;
    int q = idx % (DIN / 4);
    int d = q * 4;
    size_t row = idx / (DIN / 4);
    int l = (int)(row % HWX);
    float4 w0 = *(const float4*)&g_cw_t[0 * DIN + d];
    float4 w1 = *(const float4*)&g_cw_t[1 * DIN + d];
    float4 w2 = *(const float4*)&g_cw_t[2 * DIN + d];
    float4 b4 = *(const float4*)&cb[d];
    const float* base = g_xz + row * 2 * DIN + d;
    float4 v2 = *(const float4*)base;
    float4 v1 = make_float4(0.f, 0.f, 0.f, 0.f);
    float4 v0 = make_float4(0.f, 0.f, 0.f, 0.f);
    if (l >= 1) v1 = *(const float4*)(base - 2 * DIN);
    if (l >= 2) v0 = *(const float4*)(base - 4 * DIN);
    float a0 = b4.x + w0.x * v0.x + w1.x * v1.x + w2.x * v2.x;
    float a1 = b4.y + w0.y * v0.y + w1.y * v1.y + w2.y * v2.y;
    float a2 = b4.z + w0.z * v0.z + w1.z * v1.z + w2.z * v2.z;
    float a3 = b4.w + w0.w * v0.w + w1.w * v1.w + w2.w * v2.w;
    a0 = a0 / (1.f + __expf(-a0));
    a1 = a1 / (1.f + __expf(-a1));
    a2 = a2 / (1.f + __expf(-a2));
    a3 = a3 / (1.f + __expf(-a3));
    size_t off = row * DIN + d;
    *(float4*)&g_xmc[off] = make_float4(a0, a1, a2, a3);
    *(__nv_bfloat162*)&g_xmc_bf[off]     = __floats2bfloat162_rn(a0, a1);
    *(__nv_bfloat162*)&g_xmc_bf[off + 2] = __floats2bfloat162_rn(a2, a3);
}

// ---------------- dt_proj + softplus ------------------------------------------
__global__ void k_dtproj(const float* __restrict__ dtw, const float* __restrict__ dtb) {
    __shared__ float wT[DTR * DIN];
    __shared__ float bsm[DIN];
    __shared__ float dts[8][DTR];
    int tid = threadIdx.x;
    for (int i = tid; i < DIN * DTR; i += 256)
        wT[(i % DTR) * DIN + (i / DTR)] = dtw[i];
    for (int i = tid; i < DIN; i += 256) bsm[i] = dtb[i];
    int r0 = blockIdx.x * 8;
    if (tid < 8 * DTR) {
        int t = tid / DTR, k = tid % DTR;
        dts[t][k] = g_xdbl[(size_t)(r0 + t) * 64 + k];
    }
    __syncthreads();
    int w = tid >> 5, lane = tid & 31;
    size_t row = (size_t)(r0 + w) * DIN;
    float dk[DTR];
#pragma unroll
    for (int k = 0; k < DTR; k++) dk[k] = dts[w][k];
    for (int d = lane; d < DIN; d += 32) {
        float s = bsm[d];
#pragma unroll
        for (int k = 0; k < DTR; k++) s = fmaf(dk[k], wT[k * DIN + d], s);
        g_delta[row + d] = (s > 20.f) ? s : log1pf(expf(s));
    }
}

// ---------------- chunked selective scan: thread = (b, d, chunk) ---------------
// 16 n-states in registers, B/C staged in smem (broadcast).
__global__ void k_scanA2(const float* __restrict__ A_log) {
    int blk = blockIdx.x;                 // ((b*NCH + ch)*3 + ds)
    int ds = blk % 3;
    int t0 = blk / 3;
    int ch = t0 % NCH, b = t0 / NCH;
    int tid = threadIdx.x;                // 128
    int d = ds * 128 + tid;
    __shared__ float sB[CL][DST];
    size_t tb = (size_t)b * HWX + (size_t)ch * CL;
    for (int e = tid; e < CL * DST; e += 128) {
        int t = e >> 4, n = e & 15;
        sB[t][n] = g_xdbl[(tb + t) * 64 + 12 + n];
    }
    __syncthreads();
    float An[DST], P[DST], S[DST];
#pragma unroll
    for (int n = 0; n < DST; n++) {
        An[n] = -expf(A_log[d * DST + n]);
        P[n] = 1.f; S[n] = 0.f;
    }
    const float* pd = g_delta + tb * DIN + d;
    const float* px = g_xmc   + tb * DIN + d;
    for (int t = 0; t < CL; t++) {
        float del = pd[(size_t)t * DIN];
        float xv  = px[(size_t)t * DIN];
        float u = del * xv;
#pragma unroll
        for (int n = 0; n < DST; n++) {
            float dA = __expf(del * An[n]);
            P[n] *= dA;
            S[n] = fmaf(dA, S[n], u * sB[t][n]);
        }
    }
    size_t bse = ((size_t)(b * NCH + ch) * DST) * DIN + d;
#pragma unroll
    for (int n = 0; n < DST; n++) {
        g_cP[bse + (size_t)n * DIN] = P[n];
        g_cS[bse + (size_t)n * DIN] = S[n];
    }
}

__global__ void k_scanB2() {
    int i = blockIdx.x * 256 + threadIdx.x;   // < BB*DST*DIN
    if (i >= BB * DST * DIN) return;
    int d = i % DIN;
    int n = (i / DIN) % DST;
    int b = i / (DIN * DST);
    float h = 0.f;
    for (int ch = 0; ch < NCH; ch++) {
        size_t idx = ((size_t)(b * NCH + ch) * DST + n) * DIN + d;
        g_h0[idx] = h;
        h = fmaf(g_cP[idx], h, g_cS[idx]);
    }
}

__global__ void k_scanC2(const float* __restrict__ A_log, const float* __restrict__ Dskip) {
    int blk = blockIdx.x;
    int ds = blk % 3;
    int t0 = blk / 3;
    int ch = t0 % NCH, b = t0 / NCH;
    int tid = threadIdx.x;
    int d = ds * 128 + tid;
    __shared__ float2 sBC[CL][DST];
    size_t tb = (size_t)b * HWX + (size_t)ch * CL;
    for (int e = tid; e < CL * DST; e += 128) {
        int t = e >> 4, n = e & 15;
        sBC[t][n] = make_float2(g_xdbl[(tb + t) * 64 + 12 + n],
                                g_xdbl[(tb + t) * 64 + 28 + n]);
    }
    __syncthreads();
    float An[DST], h[DST];
    size_t bse = ((size_t)(b * NCH + ch) * DST) * DIN + d;
#pragma unroll
    for (int n = 0; n < DST; n++) {
        An[n] = -expf(A_log[d * DST + n]);
        h[n] = g_h0[bse + (size_t)n * DIN];
    }
    float Dsk = Dskip[d];
    const float* pd = g_delta + tb * DIN + d;
    const float* px = g_xmc   + tb * DIN + d;
    const float* pz = g_xz    + tb * 2 * DIN + DIN + d;
    __nv_bfloat16* py = g_ybf + tb * DIN + d;
    for (int t = 0; t < CL; t++) {
        float del = pd[(size_t)t * DIN];
        float xv  = px[(size_t)t * DIN];
        float zv  = pz[(size_t)t * 2 * DIN];
        float u = del * xv;
        float y = 0.f;
#pragma unroll
        for (int n = 0; n < DST; n++) {
            float dA = __expf(del * An[n]);
            h[n] = fmaf(dA, h[n], u * sBC[t][n].x);
            y = fmaf(h[n], sBC[t][n].y, y);
        }
        float sz = zv / (1.f + __expf(-zv));
        py[(size_t)t * DIN] = __float2bfloat16((y + xv * Dsk) * sz);
    }
}

// ---------------- x1 = x + transpose(yp) ---------------------------------------
__global__ void k_addT(const float* __restrict__ x, float* __restrict__ x1) {
    __shared__ float t[32][33];
    int b = blockIdx.z, c0 = blockIdx.y * 32, l0 = blockIdx.x * 32;
    int tx = threadIdx.x, ty = threadIdx.y;
    t[ty][tx] = g_yp[((size_t)b * HWX + l0 + ty) * CC + c0 + tx];
    __syncthreads();
    size_t idx = ((size_t)b * CC + c0 + ty) * HWX + l0 + tx;
    x1[idx] = x[idx] + t[tx][ty];
}

// ---------------- dw 3x3 conv + BN + exact GELU + residual ---------------------
__global__ void k_dw(const float* __restrict__ w, const float* __restrict__ bg,
                     const float* __restrict__ bb, const float* __restrict__ bm,
                     const float* __restrict__ bv) {
    size_t idx = (size_t)blockIdx.x * 256 + threadIdx.x;
    if (idx >= (size_t)BB * CC * HWX) return;
    int wc = (int)(idx % WWD);
    int hr = (int)((idx / WWD) % HH);
    int bc = (int)(idx / HWX);
    int c  = bc % CC;
    const float* p = g_x1 + (size_t)bc * HWX;
    float acc = 0.f;
#pragma unroll
    for (int ky = 0; ky < 3; ky++) {
        int hy = hr + ky - 1;
        if (hy < 0 || hy >= HH) continue;
#pragma unroll
        for (int kx = 0; kx < 3; kx++) {
            int wx = wc + kx - 1;
            if (wx < 0 || wx >= WWD) continue;
            acc += p[hy * WWD + wx] * __ldg(&w[c * 9 + ky * 3 + kx]);
        }
    }
    float bn = (acc - bm[c]) * rsqrtf(bv[c] + 1e-5f) * bg[c] + bb[c];
    float gl = 0.5f * bn * (1.f + erff(bn * 0.70710678118654752f));
    g_x2[idx] = g_x1[idx] + gl;
}

// ---------------- out = x2 + transpose(m) + b2 ----------------------------------
__global__ void k_final(const float* __restrict__ b2, float* __restrict__ out) {
    __shared__ float t[32][33];
    int b = blockIdx.z, c0 = blockIdx.y * 32, l0 = blockIdx.x * 32;
    int tx = threadIdx.x, ty = threadIdx.y;
    t[ty][tx] = g_m[((size_t)b * HWX + l0 + ty) * CC + c0 + tx];
    __syncthreads();
    size_t idx = ((size_t)b * CC + c0 + ty) * HWX + l0 + tx;
    out[idx] = g_x2[idx] + t[tx][ty] + b2[c0 + ty];
}

// ---------------------------------------------------------------------------
extern "C" void kernel_launch(void* const* d_in, const int* in_sizes, int n_in,
                              void* d_out, int out_size) {
    const float* x         = (const float*)d_in[0];
    const float* ln1_g     = (const float*)d_in[1];
    const float* ln1_b     = (const float*)d_in[2];
    const float* in_proj_w = (const float*)d_in[3];
    const float* conv1d_w  = (const float*)d_in[4];
    const float* conv1d_b  = (const float*)d_in[5];
    const float* x_proj_w  = (const float*)d_in[6];
    const float* dt_proj_w = (const float*)d_in[7];
    const float* dt_proj_b = (const float*)d_in[8];
    const float* A_log     = (const float*)d_in[9];
    const float* Dskip     = (const float*)d_in[10];
    const float* out_proj_w= (const float*)d_in[11];
    const float* dw_w      = (const float*)d_in[12];
    const float* bn_g      = (const float*)d_in[13];
    const float* bn_b      = (const float*)d_in[14];
    const float* bn_mean   = (const float*)d_in[15];
    const float* bn_var    = (const float*)d_in[16];
    const float* ln2_g     = (const float*)d_in[17];
    const float* ln2_b     = (const float*)d_in[18];
    const float* mlp_w1    = (const float*)d_in[19];
    const float* mlp_b1    = (const float*)d_in[20];
    const float* mlp_w2    = (const float*)d_in[21];
    const float* mlp_b2    = (const float*)d_in[22];
    float* out = (float*)d_out;

    float *p_xz, *p_xdbl, *p_yp, *p_x1, *p_x2, *p_m;
    __nv_bfloat16 *p_tokb, *p_xmcb, *p_xwb, *p_win, *p_wout, *p_w1, *p_w2,
                  *p_ybf, *p_tok2b, *p_hidb;
    cudaGetSymbolAddress((void**)&p_xz,    g_xz);
    cudaGetSymbolAddress((void**)&p_xdbl,  g_xdbl);
    cudaGetSymbolAddress((void**)&p_yp,    g_yp);
    cudaGetSymbolAddress((void**)&p_x1,    g_x1);
    cudaGetSymbolAddress((void**)&p_x2,    g_x2);
    cudaGetSymbolAddress((void**)&p_m,     g_m);
    cudaGetSymbolAddress((void**)&p_tokb,  g_tok_bf);
    cudaGetSymbolAddress((void**)&p_xmcb,  g_xmc_bf);
    cudaGetSymbolAddress((void**)&p_xwb,   g_xw_bf);
    cudaGetSymbolAddress((void**)&p_win,   g_w_in);
    cudaGetSymbolAddress((void**)&p_wout,  g_w_out);
    cudaGetSymbolAddress((void**)&p_w1,    g_w1);
    cudaGetSymbolAddress((void**)&p_w2,    g_w2);
    cudaGetSymbolAddress((void**)&p_ybf,   g_ybf);
    cudaGetSymbolAddress((void**)&p_tok2b, g_tok2_bf);
    cudaGetSymbolAddress((void**)&p_hidb,  g_hid_bf);

    // dynamic smem sizes
    const int SMP128 = (2 * 128 * 40 + 2 * 128 * 40) * 2;   // 40960
    const int SMP64  = (2 * 128 * 40 + 2 * 64  * 40) * 2;   // 30720
    const int SMG    = 128 * (128 + 4) * 4;                 // 67584 (gelu stage)
    cudaFuncSetAttribute(k_gemmbf<128, 0>, cudaFuncAttributeMaxDynamicSharedMemorySize, SMP128);
    cudaFuncSetAttribute(k_gemmbf<64,  0>, cudaFuncAttributeMaxDynamicSharedMemorySize, SMP64);
    cudaFuncSetAttribute(k_gemmbf<128, 1>, cudaFuncAttributeMaxDynamicSharedMemorySize, SMG);

    dim3 lnGrid(HWX / 32, BB);
    dim3 tGrid(HWX / 32, CC / 32, BB);
    dim3 tBlk(32, 32);
    const int CVTN = 2 * DIN * CC + CC * DIN + 4 * CC * CC + CC * 4 * CC + 3 * DIN;

    // 0,1: weight prep (independent, first — puts in_proj GEMM at profiled slot 3)
    k_padw<<<(64 * DIN + 255) / 256, 256>>>(x_proj_w);
    k_cvtw<<<(CVTN + 255) / 256, 256>>>(in_proj_w, out_proj_w, mlp_w1, mlp_w2, conv1d_w);
    // 2: LN1 -> bf16 tokens
    k_ln<<<lnGrid, 256>>>(x, ln1_g, ln1_b, p_tokb);
    // 3: in_proj (M,192)->(M,768)  [profiled]
    k_gemmbf<128, 0><<<dim3(LTOK / 128, 6), 256, SMP128>>>(p_tokb, p_win, nullptr, p_xz, nullptr, 2 * DIN, CC);
    // 4: conv1d + silu (fp32 + bf16 out)
    k_conv1d<<<(LTOK * (DIN / 4) + 255) / 256, 256>>>(conv1d_b);
    // 5: x_proj padded GEMM (M,384)->(M,64)
    k_gemmbf<64, 0><<<dim3(LTOK / 128, 1), 256, SMP64>>>(p_xmcb, p_xwb, nullptr, p_xdbl, nullptr, 64, DIN);
    // 6: dt_proj + softplus
    k_dtproj<<<LTOK / 8, 256>>>(dt_proj_w, dt_proj_b);
    // 7-9: chunked selective scan (d-per-thread)
    k_scanA2<<<BB * NCH * 3, 128>>>(A_log);
    k_scanB2<<<(BB * DST * DIN + 255) / 256, 256>>>();
    k_scanC2<<<BB * NCH * 3, 128>>>(A_log, Dskip);
    // 10: out_proj (M,384)->(M,192)
    k_gemmbf<64, 0><<<dim3(LTOK / 128, 3), 256, SMP64>>>(p_ybf, p_wout, nullptr, p_yp, nullptr, CC, DIN);
    // 11: x1 = x + y^T
    k_addT<<<tGrid, tBlk>>>(x, p_x1);
    // 12: dw conv + BN + gelu + residual
    k_dw<<<(BB * CC * HWX + 255) / 256, 256>>>(dw_w, bn_g, bn_b, bn_mean, bn_var);
    // 13: LN2 -> bf16 tokens
    k_ln<<<lnGrid, 256>>>(p_x2, ln2_g, ln2_b, p_tok2b);
    // 14: mlp1 + fused bias + gelu -> bf16 hidden
    k_gemmbf<128, 1><<<dim3(LTOK / 128, 6), 256, SMG>>>(p_tok2b, p_w1, mlp_b1, nullptr, p_hidb, 4 * CC, CC);
    // 15: mlp2 (M,768)->(M,192)
    k_gemmbf<64, 0><<<dim3(LTOK / 128, 3), 256, SMP64>>>(p_hidb, p_w2, nullptr, p_m, nullptr, CC, 4 * CC);
    // 16: out = x2 + m^T + b2
    k_final<<<tGrid, tBlk>>>(mlp_b2, out);
}

// round 5
// speedup vs baseline: 12.4954x; 1.1086x over previous
#include <cuda_runtime.h>
#include <cuda_bf16.h>
#include <mma.h>
#include <cstdint>

using namespace nvcuda;

#define BB   4
#define CC   192
#define HH   56
#define WWD  56
#define HWX  3136
#define LTOK 12544     // B*H*W
#define DIN  384
#define DST  16
#define DTR  12
#define NCH  56        // scan chunks
#define CL   56        // chunk length (NCH*CL == HWX)

// ---------------- scratch (device globals; no allocation allowed) ----------
__device__ __nv_bfloat16 g_tok_bf [(size_t)LTOK * CC];
__device__ float         g_xz     [(size_t)LTOK * 2 * DIN];
__device__ __nv_bfloat16 g_xmc_bf [(size_t)LTOK * DIN];
__device__ float         g_xdbl   [(size_t)LTOK * 64];   // dt[0:12], B[12:28], C[28:44]
__device__ __nv_bfloat16 g_xw_bf  [64 * DIN];
__device__ __nv_bfloat16 g_w_in   [2 * DIN * CC];
__device__ __nv_bfloat16 g_w_out  [CC * DIN];
__device__ __nv_bfloat16 g_w1     [4 * CC * CC];
__device__ __nv_bfloat16 g_w2     [CC * 4 * CC];
__device__ float         g_cw_t   [3 * DIN];              // transposed conv weights
__device__ float         g_delta  [(size_t)LTOK * DIN];
__device__ __nv_bfloat16 g_ybf    [(size_t)LTOK * DIN];
__device__ float         g_x1     [(size_t)BB * CC * HWX];
__device__ float         g_x2     [(size_t)BB * CC * HWX];
__device__ __nv_bfloat16 g_tok2_bf[(size_t)LTOK * CC];
__device__ __nv_bfloat16 g_hid_bf [(size_t)LTOK * 4 * CC];
__device__ float         g_cP     [(size_t)BB * NCH * DST * DIN];
__device__ float         g_cS     [(size_t)BB * NCH * DST * DIN];
__device__ float         g_h0     [(size_t)BB * NCH * DST * DIN];

// ---------------- cp.async helpers ------------------------------------------
__device__ __forceinline__ void cp_async16(void* sdst, const void* gsrc) {
    uint32_t s = (uint32_t)__cvta_generic_to_shared(sdst);
    asm volatile("cp.async.cg.shared.global [%0], [%1], 16;\n" :: "r"(s), "l"(gsrc) : "memory");
}
__device__ __forceinline__ void cp_commit() {
    asm volatile("cp.async.commit_group;\n" ::: "memory");
}
__device__ __forceinline__ void cp_wait0() {
    asm volatile("cp.async.wait_group 0;\n" ::: "memory");
}

// ---------------- weight prep (all-in-one) ------------------------------------
__global__ void k_cvtw(const float* __restrict__ win, const float* __restrict__ wout,
                       const float* __restrict__ w1, const float* __restrict__ w2,
                       const float* __restrict__ cw, const float* __restrict__ xw) {
    const int N1 = 2 * DIN * CC, N2 = CC * DIN, N3 = 4 * CC * CC, N4 = CC * 4 * CC,
              N5 = 3 * DIN, N6 = 64 * DIN;
    int i = blockIdx.x * 256 + threadIdx.x;
    if (i < N1) { g_w_in[i] = __float2bfloat16(win[i]); return; }
    i -= N1;
    if (i < N2) { g_w_out[i] = __float2bfloat16(wout[i]); return; }
    i -= N2;
    if (i < N3) { g_w1[i] = __float2bfloat16(w1[i]); return; }
    i -= N3;
    if (i < N4) { g_w2[i] = __float2bfloat16(w2[i]); return; }
    i -= N4;
    if (i < N5) { int d = i % DIN, k = i / DIN; g_cw_t[k * DIN + d] = cw[d * 3 + k]; return; }
    i -= N5;
    if (i < N6) { int r = i / DIN; g_xw_bf[i] = __float2bfloat16((r < 44) ? xw[i] : 0.f); }
}

// ---------------- LayerNorm over C with NCHW->(M,C) transpose, bf16 out ------
__global__ void k_ln(const float* __restrict__ in, const float* __restrict__ g,
                     const float* __restrict__ bta, __nv_bfloat16* __restrict__ out) {
    __shared__ float sh[32 * 193];
    int b  = blockIdx.y;
    int l0 = blockIdx.x * 32;
    int tx = threadIdx.x & 31;
    int ty = threadIdx.x >> 5;
    const size_t base = (size_t)b * CC * HWX;
    for (int c = ty; c < CC; c += 8)
        sh[tx * 193 + c] = in[base + (size_t)c * HWX + l0 + tx];
    __syncthreads();
    int lane = tx;
    for (int tk = ty * 4; tk < ty * 4 + 4; tk++) {
        float s = 0.f, s2 = 0.f;
#pragma unroll
        for (int j = 0; j < 6; j++) {
            float v = sh[tk * 193 + lane + j * 32];
            s += v; s2 += v * v;
        }
#pragma unroll
        for (int o = 16; o; o >>= 1) {
            s  += __shfl_xor_sync(0xffffffffu, s, o);
            s2 += __shfl_xor_sync(0xffffffffu, s2, o);
        }
        float m  = s * (1.f / CC);
        float va = s2 * (1.f / CC) - m * m;
        float rs = rsqrtf(va + 1e-5f);
        size_t row = ((size_t)b * HWX + l0 + tk) * CC;
#pragma unroll
        for (int j = 0; j < 6; j++) {
            int c = lane + j * 32;
            out[row + c] = __float2bfloat16((sh[tk * 193 + c] - m) * rs * g[c] + bta[c]);
        }
    }
}

// ---------------- pipelined bf16 WMMA GEMM ------------------------------------
// C[M,N] = A[M,K] * W[N,K]^T.
// EPI 0: plain fp32 store (row-major M,N)
// EPI 1: bias+GELU -> bf16 store (row-major)
// EPI 2: transposed NCHW store: Cf[b,c,l] = resid[b,c,l] + val
// EPI 3: transposed NCHW store: Cf[b,c,l] = resid[b,c,l] + val + bias[c]
template<int BN, int EPI>
__global__ void k_gemmbf(const __nv_bfloat16* __restrict__ A,
                         const __nv_bfloat16* __restrict__ Bw,
                         const float* __restrict__ bias,
                         const float* __restrict__ resid,
                         float* __restrict__ Cf, __nv_bfloat16* __restrict__ Cbf,
                         int N, int K) {
    extern __shared__ char smraw[];
    __nv_bfloat16* sA = (__nv_bfloat16*)smraw;           // [2][128][40]
    __nv_bfloat16* sB = sA + 2 * 128 * 40;               // [2][BN][40]
    constexpr int WN = (BN == 128) ? 64 : 32;
    constexpr int NF = WN / 16;
    int tid = threadIdx.x;
    int wid = tid >> 5;
    int m0 = blockIdx.x * 128, n0 = blockIdx.y * BN;
    int wm = (wid >> 1) * 32, wn = (wid & 1) * WN;

    wmma::fragment<wmma::accumulator, 16, 16, 16, float> acc[2][NF];
#pragma unroll
    for (int i = 0; i < 2; i++)
#pragma unroll
        for (int j = 0; j < NF; j++) wmma::fill_fragment(acc[i][j], 0.f);

    const int T = K >> 5;

#define LOAD_A(buf, k0)                                                            \
    {                                                                              \
        _Pragma("unroll")                                                          \
        for (int s = 0; s < 2; s++) {                                              \
            int c = tid + 256 * s;                                                 \
            int r = c >> 2, co = (c & 3) * 8;                                      \
            cp_async16(sA + (buf) * 128 * 40 + r * 40 + co,                        \
                       A + (size_t)(m0 + r) * K + (k0) + co);                      \
        }                                                                          \
    }
#define LOAD_B(buf, k0)                                                            \
    {                                                                              \
        _Pragma("unroll")                                                          \
        for (int s = 0; s < BN / 64; s++) {                                        \
            int c = tid + 256 * s;                                                 \
            int r = c >> 2, co = (c & 3) * 8;                                      \
            cp_async16(sB + (buf) * BN * 40 + r * 40 + co,                         \
                       Bw + (size_t)(n0 + r) * K + (k0) + co);                     \
        }                                                                          \
    }

    LOAD_A(0, 0) LOAD_B(0, 0)
    cp_commit();

    for (int it = 0; it < T; it++) {
        cp_wait0();
        __syncthreads();
        int buf = it & 1;
        if (it + 1 < T) {
            LOAD_A(buf ^ 1, (it + 1) << 5)
            LOAD_B(buf ^ 1, (it + 1) << 5)
            cp_commit();
        }
        const __nv_bfloat16* Ab = sA + buf * 128 * 40;
        const __nv_bfloat16* Bb = sB + buf * BN * 40;
#pragma unroll
        for (int kk = 0; kk < 2; kk++) {
            wmma::fragment<wmma::matrix_a, 16, 16, 16, __nv_bfloat16, wmma::row_major> af[2];
            wmma::fragment<wmma::matrix_b, 16, 16, 16, __nv_bfloat16, wmma::col_major> bfm[NF];
#pragma unroll
            for (int i = 0; i < 2; i++)
                wmma::load_matrix_sync(af[i], Ab + (wm + 16 * i) * 40 + kk * 16, 40);
#pragma unroll
            for (int j = 0; j < NF; j++)
                wmma::load_matrix_sync(bfm[j], Bb + (wn + 16 * j) * 40 + kk * 16, 40);
#pragma unroll
            for (int i = 0; i < 2; i++)
#pragma unroll
                for (int j = 0; j < NF; j++)
                    wmma::mma_sync(acc[i][j], af[i], bfm[j], acc[i][j]);
        }
        __syncthreads();
    }
#undef LOAD_A
#undef LOAD_B

    if (EPI == 0) {
#pragma unroll
        for (int i = 0; i < 2; i++)
#pragma unroll
            for (int j = 0; j < NF; j++)
                wmma::store_matrix_sync(&Cf[(size_t)(m0 + wm + 16 * i) * N + n0 + wn + 16 * j],
                                        acc[i][j], N, wmma::mem_row_major);
    } else if (EPI == 1) {
        constexpr int PAD = BN + 4;
        float* stage = (float*)smraw;
        __syncthreads();
#pragma unroll
        for (int i = 0; i < 2; i++)
#pragma unroll
            for (int j = 0; j < NF; j++)
                wmma::store_matrix_sync(&stage[(wm + 16 * i) * PAD + wn + 16 * j],
                                        acc[i][j], PAD, wmma::mem_row_major);
        __syncthreads();
        constexpr int V = BN / 4;
        for (int idx = tid; idx < 128 * V; idx += 256) {
            int row = idx / V;
            int col = (idx % V) * 4;
            float4 v = *(const float4*)&stage[row * PAD + col];
            float4 bo = *(const float4*)&bias[n0 + col];
            float r[4] = {v.x + bo.x, v.y + bo.y, v.z + bo.z, v.w + bo.w};
#pragma unroll
            for (int q = 0; q < 4; q++)
                r[q] = 0.5f * r[q] * (1.f + erff(r[q] * 0.70710678118654752f));
            size_t off = (size_t)(m0 + row) * N + n0 + col;
            *(__nv_bfloat162*)&Cbf[off]     = __floats2bfloat162_rn(r[0], r[1]);
            *(__nv_bfloat162*)&Cbf[off + 2] = __floats2bfloat162_rn(r[2], r[3]);
        }
    } else {
        // EPI 2/3: transposed write to NCHW with residual (+bias for EPI 3)
        constexpr int PAD = BN + 4;
        float* stage = (float*)smraw;   // 128*PAD*4 bytes
        __syncthreads();
#pragma unroll
        for (int i = 0; i < 2; i++)
#pragma unroll
            for (int j = 0; j < NF; j++)
                wmma::store_matrix_sync(&stage[(wm + 16 * i) * PAD + wn + 16 * j],
                                        acc[i][j], PAD, wmma::mem_row_major);
        __syncthreads();
        int lane = tid & 31;
        for (int col = wid; col < BN; col += 8) {
            int c = n0 + col;
            float badd = (EPI == 3) ? bias[c] : 0.f;
#pragma unroll
            for (int rg = 0; rg < 4; rg++) {
                int row = rg * 32 + lane;
                int m = m0 + row;
                int b = m / HWX, l = m - b * HWX;
                size_t idx = ((size_t)b * CC + c) * HWX + l;
                Cf[idx] = resid[idx] + stage[row * PAD + col] + badd;
            }
        }
    }
}

// ---------------- causal depthwise conv1d (k=3) + SiLU, bf16 out ---------------
__global__ void k_conv1d(const float* __restrict__ cb) {
    int idx = blockIdx.x * 256 + threadIdx.x;
    if (idx >= LTOK * (DIN / 4)) return;
    int q = idx % (DIN / 4);
    int d = q * 4;
    size_t row = idx / (DIN / 4);
    int l = (int)(row % HWX);
    float4 w0 = *(const float4*)&g_cw_t[0 * DIN + d];
    float4 w1 = *(const float4*)&g_cw_t[1 * DIN + d];
    float4 w2 = *(const float4*)&g_cw_t[2 * DIN + d];
    float4 b4 = *(const float4*)&cb[d];
    const float* base = g_xz + row * 2 * DIN + d;
    float4 v2 = *(const float4*)base;
    float4 v1 = make_float4(0.f, 0.f, 0.f, 0.f);
    float4 v0 = make_float4(0.f, 0.f, 0.f, 0.f);
    if (l >= 1) v1 = *(const float4*)(base - 2 * DIN);
    if (l >= 2) v0 = *(const float4*)(base - 4 * DIN);
    float a0 = b4.x + w0.x * v0.x + w1.x * v1.x + w2.x * v2.x;
    float a1 = b4.y + w0.y * v0.y + w1.y * v1.y + w2.y * v2.y;
    float a2 = b4.z + w0.z * v0.z + w1.z * v1.z + w2.z * v2.z;
    float a3 = b4.w + w0.w * v0.w + w1.w * v1.w + w2.w * v2.w;
    a0 = a0 / (1.f + __expf(-a0));
    a1 = a1 / (1.f + __expf(-a1));
    a2 = a2 / (1.f + __expf(-a2));
    a3 = a3 / (1.f + __expf(-a3));
    size_t off = row * DIN + d;
    *(__nv_bfloat162*)&g_xmc_bf[off]     = __floats2bfloat162_rn(a0, a1);
    *(__nv_bfloat162*)&g_xmc_bf[off + 2] = __floats2bfloat162_rn(a2, a3);
}

// ---------------- dt_proj + softplus ------------------------------------------
__global__ void k_dtproj(const float* __restrict__ dtw, const float* __restrict__ dtb) {
    __shared__ float wT[DTR * DIN];
    __shared__ float bsm[DIN];
    __shared__ float dts[8][DTR];
    int tid = threadIdx.x;
    for (int i = tid; i < DIN * DTR; i += 256)
        wT[(i % DTR) * DIN + (i / DTR)] = dtw[i];
    for (int i = tid; i < DIN; i += 256) bsm[i] = dtb[i];
    int r0 = blockIdx.x * 8;
    if (tid < 8 * DTR) {
        int t = tid / DTR, k = tid % DTR;
        dts[t][k] = g_xdbl[(size_t)(r0 + t) * 64 + k];
    }
    __syncthreads();
    int w = tid >> 5, lane = tid & 31;
    size_t row = (size_t)(r0 + w) * DIN;
    float dk[DTR];
#pragma unroll
    for (int k = 0; k < DTR; k++) dk[k] = dts[w][k];
    for (int d = lane; d < DIN; d += 32) {
        float s = bsm[d];
#pragma unroll
        for (int k = 0; k < DTR; k++) s = fmaf(dk[k], wT[k * DIN + d], s);
        g_delta[row + d] = (s > 20.f) ? s : log1pf(expf(s));
    }
}

// ---------------- chunked selective scan: thread = (b, d, chunk) ---------------
__global__ void k_scanA2(const float* __restrict__ A_log) {
    int blk = blockIdx.x;                 // ((b*NCH + ch)*3 + ds)
    int ds = blk % 3;
    int t0 = blk / 3;
    int ch = t0 % NCH, b = t0 / NCH;
    int tid = threadIdx.x;                // 128
    int d = ds * 128 + tid;
    __shared__ float sB[CL][DST];
    size_t tb = (size_t)b * HWX + (size_t)ch * CL;
    for (int e = tid; e < CL * DST; e += 128) {
        int t = e >> 4, n = e & 15;
        sB[t][n] = g_xdbl[(tb + t) * 64 + 12 + n];
    }
    __syncthreads();
    float An[DST], P[DST], S[DST];
#pragma unroll
    for (int n = 0; n < DST; n++) {
        An[n] = -expf(A_log[d * DST + n]);
        P[n] = 1.f; S[n] = 0.f;
    }
    const float*         pd = g_delta  + tb * DIN + d;
    const __nv_bfloat16* px = g_xmc_bf + tb * DIN + d;
    for (int t = 0; t < CL; t++) {
        float del = pd[(size_t)t * DIN];
        float xv  = __bfloat162float(px[(size_t)t * DIN]);
        float u = del * xv;
#pragma unroll
        for (int n = 0; n < DST; n++) {
            float dA = __expf(del * An[n]);
            P[n] *= dA;
            S[n] = fmaf(dA, S[n], u * sB[t][n]);
        }
    }
    size_t bse = ((size_t)(b * NCH + ch) * DST) * DIN + d;
#pragma unroll
    for (int n = 0; n < DST; n++) {
        g_cP[bse + (size_t)n * DIN] = P[n];
        g_cS[bse + (size_t)n * DIN] = S[n];
    }
}

__global__ void k_scanB2() {
    int i = blockIdx.x * 256 + threadIdx.x;   // < BB*DST*DIN
    if (i >= BB * DST * DIN) return;
    int d = i % DIN;
    int n = (i / DIN) % DST;
    int b = i / (DIN * DST);
    float h = 0.f;
    for (int ch = 0; ch < NCH; ch++) {
        size_t idx = ((size_t)(b * NCH + ch) * DST + n) * DIN + d;
        g_h0[idx] = h;
        h = fmaf(g_cP[idx], h, g_cS[idx]);
    }
}

__global__ void k_scanC2(const float* __restrict__ A_log, const float* __restrict__ Dskip) {
    int blk = blockIdx.x;
    int ds = blk % 3;
    int t0 = blk / 3;
    int ch = t0 % NCH, b = t0 / NCH;
    int tid = threadIdx.x;
    int d = ds * 128 + tid;
    __shared__ float2 sBC[CL][DST];
    size_t tb = (size_t)b * HWX + (size_t)ch * CL;
    for (int e = tid; e < CL * DST; e += 128) {
        int t = e >> 4, n = e & 15;
        sBC[t][n] = make_float2(g_xdbl[(tb + t) * 64 + 12 + n],
                                g_xdbl[(tb + t) * 64 + 28 + n]);
    }
    __syncthreads();
    float An[DST], h[DST];
    size_t bse = ((size_t)(b * NCH + ch) * DST) * DIN + d;
#pragma unroll
    for (int n = 0; n < DST; n++) {
        An[n] = -expf(A_log[d * DST + n]);
        h[n] = g_h0[bse + (size_t)n * DIN];
    }
    float Dsk = Dskip[d];
    const float*         pd = g_delta  + tb * DIN + d;
    const __nv_bfloat16* px = g_xmc_bf + tb * DIN + d;
    const float*         pz = g_xz     + tb * 2 * DIN + DIN + d;
    __nv_bfloat16*       py = g_ybf    + tb * DIN + d;
    for (int t = 0; t < CL; t++) {
        float del = pd[(size_t)t * DIN];
        float xv  = __bfloat162float(px[(size_t)t * DIN]);
        float zv  = pz[(size_t)t * 2 * DIN];
        float u = del * xv;
        float y = 0.f;
#pragma unroll
        for (int n = 0; n < DST; n++) {
            float dA = __expf(del * An[n]);
            h[n] = fmaf(dA, h[n], u * sBC[t][n].x);
            y = fmaf(h[n], sBC[t][n].y, y);
        }
        float sz = zv / (1.f + __expf(-zv));
        py[(size_t)t * DIN] = __float2bfloat16((y + xv * Dsk) * sz);
    }
}

// ---------------- dw 3x3 conv + BN + exact GELU + residual (smem tiled) -------
__global__ void k_dw(const float* __restrict__ w, const float* __restrict__ bg,
                     const float* __restrict__ bb, const float* __restrict__ bm,
                     const float* __restrict__ bv) {
    __shared__ float t[16][58];
    int strip = blockIdx.x;          // 0..3, 14 rows each
    int c = blockIdx.y;
    int b = blockIdx.z;
    int tid = threadIdx.x;
    const float* plane = g_x1 + ((size_t)b * CC + c) * HWX;

    for (int i = tid; i < 16 * 58; i += 256) {
        int r = i / 58, cc = i % 58;
        int hy = strip * 14 - 1 + r;
        int wx = cc - 1;
        t[r][cc] = (hy >= 0 && hy < HH && wx >= 0 && wx < WWD) ? plane[hy * WWD + wx] : 0.f;
    }
    __syncthreads();

    float w9[9];
#pragma unroll
    for (int k = 0; k < 9; k++) w9[k] = __ldg(&w[c * 9 + k]);
    float mean = bm[c], g = bg[c], beta = bb[c];
    float rs = rsqrtf(bv[c] + 1e-5f);

    float* outp = g_x2 + ((size_t)b * CC + c) * HWX;
    for (int i = tid; i < 14 * WWD; i += 256) {
        int r = i / WWD, wc = i % WWD;
        float acc = 0.f;
#pragma unroll
        for (int ky = 0; ky < 3; ky++)
#pragma unroll
            for (int kx = 0; kx < 3; kx++)
                acc = fmaf(t[r + ky][wc + kx], w9[ky * 3 + kx], acc);
        float bn = (acc - mean) * rs * g + beta;
        float gl = 0.5f * bn * (1.f + erff(bn * 0.70710678118654752f));
        outp[(strip * 14 + r) * WWD + wc] = t[r + 1][wc + 1] + gl;
    }
}

// ---------------------------------------------------------------------------
extern "C" void kernel_launch(void* const* d_in, const int* in_sizes, int n_in,
                              void* d_out, int out_size) {
    const float* x         = (const float*)d_in[0];
    const float* ln1_g     = (const float*)d_in[1];
    const float* ln1_b     = (const float*)d_in[2];
    const float* in_proj_w = (const float*)d_in[3];
    const float* conv1d_w  = (const float*)d_in[4];
    const float* conv1d_b  = (const float*)d_in[5];
    const float* x_proj_w  = (const float*)d_in[6];
    const float* dt_proj_w = (const float*)d_in[7];
    const float* dt_proj_b = (const float*)d_in[8];
    const float* A_log     = (const float*)d_in[9];
    const float* Dskip     = (const float*)d_in[10];
    const float* out_proj_w= (const float*)d_in[11];
    const float* dw_w      = (const float*)d_in[12];
    const float* bn_g      = (const float*)d_in[13];
    const float* bn_b      = (const float*)d_in[14];
    const float* bn_mean   = (const float*)d_in[15];
    const float* bn_var    = (const float*)d_in[16];
    const float* ln2_g     = (const float*)d_in[17];
    const float* ln2_b     = (const float*)d_in[18];
    const float* mlp_w1    = (const float*)d_in[19];
    const float* mlp_b1    = (const float*)d_in[20];
    const float* mlp_w2    = (const float*)d_in[21];
    const float* mlp_b2    = (const float*)d_in[22];
    float* out = (float*)d_out;

    float *p_xz, *p_xdbl, *p_x1, *p_x2;
    __nv_bfloat16 *p_tokb, *p_xmcb, *p_xwb, *p_win, *p_wout, *p_w1, *p_w2,
                  *p_ybf, *p_tok2b, *p_hidb;
    cudaGetSymbolAddress((void**)&p_xz,    g_xz);
    cudaGetSymbolAddress((void**)&p_xdbl,  g_xdbl);
    cudaGetSymbolAddress((void**)&p_x1,    g_x1);
    cudaGetSymbolAddress((void**)&p_x2,    g_x2);
    cudaGetSymbolAddress((void**)&p_tokb,  g_tok_bf);
    cudaGetSymbolAddress((void**)&p_xmcb,  g_xmc_bf);
    cudaGetSymbolAddress((void**)&p_xwb,   g_xw_bf);
    cudaGetSymbolAddress((void**)&p_win,   g_w_in);
    cudaGetSymbolAddress((void**)&p_wout,  g_w_out);
    cudaGetSymbolAddress((void**)&p_w1,    g_w1);
    cudaGetSymbolAddress((void**)&p_w2,    g_w2);
    cudaGetSymbolAddress((void**)&p_ybf,   g_ybf);
    cudaGetSymbolAddress((void**)&p_tok2b, g_tok2_bf);
    cudaGetSymbolAddress((void**)&p_hidb,  g_hid_bf);

    // dynamic smem sizes
    const int SMP128 = (2 * 128 * 40 + 2 * 128 * 40) * 2;   // 40960
    const int SMP64  = (2 * 128 * 40 + 2 * 64  * 40) * 2;   // 30720
    const int SMG    = 128 * (128 + 4) * 4;                 // 67584 (EPI1 stage)
    const int SMT    = 128 * (64 + 4) * 4;                  // 34816 (EPI2/3 stage)
    cudaFuncSetAttribute(k_gemmbf<128, 0>, cudaFuncAttributeMaxDynamicSharedMemorySize, SMP128);
    cudaFuncSetAttribute(k_gemmbf<64,  0>, cudaFuncAttributeMaxDynamicSharedMemorySize, SMP64);
    cudaFuncSetAttribute(k_gemmbf<128, 1>, cudaFuncAttributeMaxDynamicSharedMemorySize, SMG);
    cudaFuncSetAttribute(k_gemmbf<64,  2>, cudaFuncAttributeMaxDynamicSharedMemorySize, SMT);
    cudaFuncSetAttribute(k_gemmbf<64,  3>, cudaFuncAttributeMaxDynamicSharedMemorySize, SMT);

    dim3 lnGrid(HWX / 32, BB);
    const int CVTN = 2 * DIN * CC + CC * DIN + 4 * CC * CC + CC * 4 * CC + 3 * DIN + 64 * DIN;

    // 0: weight prep
    k_cvtw<<<(CVTN + 255) / 256, 256>>>(in_proj_w, out_proj_w, mlp_w1, mlp_w2, conv1d_w, x_proj_w);
    // 1: LN1 -> bf16 tokens
    k_ln<<<lnGrid, 256>>>(x, ln1_g, ln1_b, p_tokb);
    // 2: in_proj (M,192)->(M,768)
    k_gemmbf<128, 0><<<dim3(LTOK / 128, 6), 256, SMP128>>>(p_tokb, p_win, nullptr, nullptr, p_xz, nullptr, 2 * DIN, CC);
    // 3: conv1d + silu -> bf16  [profiled slot]
    k_conv1d<<<(LTOK * (DIN / 4) + 255) / 256, 256>>>(conv1d_b);
    // 4: x_proj padded GEMM (M,384)->(M,64)
    k_gemmbf<64, 0><<<dim3(LTOK / 128, 1), 256, SMP64>>>(p_xmcb, p_xwb, nullptr, nullptr, p_xdbl, nullptr, 64, DIN);
    // 5: dt_proj + softplus
    k_dtproj<<<LTOK / 8, 256>>>(dt_proj_w, dt_proj_b);
    // 6-8: chunked selective scan
    k_scanA2<<<BB * NCH * 3, 128>>>(A_log);
    k_scanB2<<<(BB * DST * DIN + 255) / 256, 256>>>();
    k_scanC2<<<BB * NCH * 3, 128>>>(A_log, Dskip);
    // 9: out_proj + fused transpose + residual -> x1 (NCHW)
    k_gemmbf<64, 2><<<dim3(LTOK / 128, 3), 256, SMT>>>(p_ybf, p_wout, nullptr, x, p_x1, nullptr, CC, DIN);
    // 10: dw conv + BN + gelu + residual -> x2
    k_dw<<<dim3(4, CC, BB), 256>>>(dw_w, bn_g, bn_b, bn_mean, bn_var);
    // 11: LN2 -> bf16 tokens
    k_ln<<<lnGrid, 256>>>(p_x2, ln2_g, ln2_b, p_tok2b);
    // 12: mlp1 + fused bias + gelu -> bf16 hidden
    k_gemmbf<128, 1><<<dim3(LTOK / 128, 6), 256, SMG>>>(p_tok2b, p_w1, mlp_b1, nullptr, nullptr, p_hidb, 4 * CC, CC);
    // 13: mlp2 + fused transpose + residual + bias -> out (NCHW)
    k_gemmbf<64, 3><<<dim3(LTOK / 128, 3), 256, SMT>>>(p_hidb, p_w2, mlp_b2, p_x2, out, nullptr, CC, 4 * CC);
}

// round 6
// speedup vs baseline: 13.6024x; 1.0886x over previous
#include <cuda_runtime.h>
#include <cuda_bf16.h>
#include <mma.h>
#include <cstdint>

using namespace nvcuda;

#define BB   4
#define CC   192
#define HH   56
#define WWD  56
#define HWX  3136
#define LTOK 12544     // B*H*W
#define DIN  384
#define DST  16
#define DTR  12
#define NCH  56        // scan chunks
#define CL   56        // chunk length (NCH*CL == HWX)

// ---------------- scratch (device globals; no allocation allowed) ----------
__device__ __nv_bfloat16 g_tok_bf [(size_t)LTOK * CC];
__device__ __nv_bfloat16 g_xz     [(size_t)LTOK * 2 * DIN];   // bf16 now
__device__ __nv_bfloat16 g_xmc_bf [(size_t)LTOK * DIN];
__device__ float         g_xdbl   [(size_t)LTOK * 64];   // dt[0:12], B[12:28], C[28:44]
__device__ __nv_bfloat16 g_xw_bf  [64 * DIN];
__device__ __nv_bfloat16 g_w_in   [2 * DIN * CC];
__device__ __nv_bfloat16 g_w_out  [CC * DIN];
__device__ __nv_bfloat16 g_w1     [4 * CC * CC];
__device__ __nv_bfloat16 g_w2     [CC * 4 * CC];
__device__ float         g_cw_t   [3 * DIN];              // transposed conv weights
__device__ __nv_bfloat16 g_ybf    [(size_t)LTOK * DIN];
__device__ float         g_x1     [(size_t)BB * CC * HWX];
__device__ float         g_x2     [(size_t)BB * CC * HWX];
__device__ __nv_bfloat16 g_tok2_bf[(size_t)LTOK * CC];
__device__ __nv_bfloat16 g_hid_bf [(size_t)LTOK * 4 * CC];
__device__ float         g_cP     [(size_t)BB * NCH * DST * DIN];
__device__ float         g_cS     [(size_t)BB * NCH * DST * DIN];
__device__ float         g_h0     [(size_t)BB * NCH * DST * DIN];

// ---------------- cp.async helpers ------------------------------------------
__device__ __forceinline__ void cp_async16(void* sdst, const void* gsrc) {
    uint32_t s = (uint32_t)__cvta_generic_to_shared(sdst);
    asm volatile("cp.async.cg.shared.global [%0], [%1], 16;\n" :: "r"(s), "l"(gsrc) : "memory");
}
__device__ __forceinline__ void cp_commit() {
    asm volatile("cp.async.commit_group;\n" ::: "memory");
}
__device__ __forceinline__ void cp_wait1() {
    asm volatile("cp.async.wait_group 1;\n" ::: "memory");
}

__device__ __forceinline__ float4 ld_bf4(const __nv_bfloat16* p) {
    __nv_bfloat162 a = *(const __nv_bfloat162*)p;
    __nv_bfloat162 b = *(const __nv_bfloat162*)(p + 2);
    float2 fa = __bfloat1622float2(a), fb = __bfloat1622float2(b);
    return make_float4(fa.x, fa.y, fb.x, fb.y);
}

// ---------------- weight prep (all-in-one) ------------------------------------
__global__ void k_cvtw(const float* __restrict__ win, const float* __restrict__ wout,
                       const float* __restrict__ w1, const float* __restrict__ w2,
                       const float* __restrict__ cw, const float* __restrict__ xw) {
    const int N1 = 2 * DIN * CC, N2 = CC * DIN, N3 = 4 * CC * CC, N4 = CC * 4 * CC,
              N5 = 3 * DIN, N6 = 64 * DIN;
    int i = blockIdx.x * 256 + threadIdx.x;
    if (i < N1) { g_w_in[i] = __float2bfloat16(win[i]); return; }
    i -= N1;
    if (i < N2) { g_w_out[i] = __float2bfloat16(wout[i]); return; }
    i -= N2;
    if (i < N3) { g_w1[i] = __float2bfloat16(w1[i]); return; }
    i -= N3;
    if (i < N4) { g_w2[i] = __float2bfloat16(w2[i]); return; }
    i -= N4;
    if (i < N5) { int d = i % DIN, k = i / DIN; g_cw_t[k * DIN + d] = cw[d * 3 + k]; return; }
    i -= N5;
    if (i < N6) { int r = i / DIN; g_xw_bf[i] = __float2bfloat16((r < 44) ? xw[i] : 0.f); }
}

// ---------------- LayerNorm over C with NCHW->(M,C) transpose, bf16 out ------
__global__ void k_ln(const float* __restrict__ in, const float* __restrict__ g,
                     const float* __restrict__ bta, __nv_bfloat16* __restrict__ out) {
    __shared__ float sh[32 * 193];
    int b  = blockIdx.y;
    int l0 = blockIdx.x * 32;
    int tx = threadIdx.x & 31;
    int ty = threadIdx.x >> 5;
    const size_t base = (size_t)b * CC * HWX;
    for (int c = ty; c < CC; c += 8)
        sh[tx * 193 + c] = in[base + (size_t)c * HWX + l0 + tx];
    __syncthreads();
    int lane = tx;
    for (int tk = ty * 4; tk < ty * 4 + 4; tk++) {
        float s = 0.f, s2 = 0.f;
#pragma unroll
        for (int j = 0; j < 6; j++) {
            float v = sh[tk * 193 + lane + j * 32];
            s += v; s2 += v * v;
        }
#pragma unroll
        for (int o = 16; o; o >>= 1) {
            s  += __shfl_xor_sync(0xffffffffu, s, o);
            s2 += __shfl_xor_sync(0xffffffffu, s2, o);
        }
        float m  = s * (1.f / CC);
        float va = s2 * (1.f / CC) - m * m;
        float rs = rsqrtf(va + 1e-5f);
        size_t row = ((size_t)b * HWX + l0 + tk) * CC;
#pragma unroll
        for (int j = 0; j < 6; j++) {
            int c = lane + j * 32;
            out[row + c] = __float2bfloat16((sh[tk * 193 + c] - m) * rs * g[c] + bta[c]);
        }
    }
}

// ---------------- 3-stage pipelined bf16 WMMA GEMM ----------------------------
// C[M,N] = A[M,K] * W[N,K]^T.
// EPI 0: plain fp32 store (row-major M,N)
// EPI 1: bias+GELU -> bf16 store (row-major)
// EPI 2: transposed NCHW store: Cf[b,c,l] = resid[b,c,l] + val
// EPI 3: transposed NCHW store: Cf[b,c,l] = resid[b,c,l] + val + bias[c]
// EPI 4: plain bf16 store (row-major)
template<int BN, int EPI>
__global__ void k_gemmbf(const __nv_bfloat16* __restrict__ A,
                         const __nv_bfloat16* __restrict__ Bw,
                         const float* __restrict__ bias,
                         const float* __restrict__ resid,
                         float* __restrict__ Cf, __nv_bfloat16* __restrict__ Cbf,
                         int N, int K) {
    extern __shared__ char smraw[];
    __nv_bfloat16* sA = (__nv_bfloat16*)smraw;           // [3][128][40]
    __nv_bfloat16* sB = sA + 3 * 128 * 40;               // [3][BN][40]
    constexpr int WN = (BN == 128) ? 64 : 32;
    constexpr int NF = WN / 16;
    int tid = threadIdx.x;
    int wid = tid >> 5;
    int m0 = blockIdx.x * 128, n0 = blockIdx.y * BN;
    int wm = (wid >> 1) * 32, wn = (wid & 1) * WN;

    wmma::fragment<wmma::accumulator, 16, 16, 16, float> acc[2][NF];
#pragma unroll
    for (int i = 0; i < 2; i++)
#pragma unroll
        for (int j = 0; j < NF; j++) wmma::fill_fragment(acc[i][j], 0.f);

    const int T = K >> 5;

#define LOAD_A(buf, k0)                                                            \
    {                                                                              \
        _Pragma("unroll")                                                          \
        for (int s = 0; s < 2; s++) {                                              \
            int c = tid + 256 * s;                                                 \
            int r = c >> 2, co = (c & 3) * 8;                                      \
            cp_async16(sA + (buf) * 128 * 40 + r * 40 + co,                        \
                       A + (size_t)(m0 + r) * K + (k0) + co);                      \
        }                                                                          \
    }
#define LOAD_B(buf, k0)                                                            \
    {                                                                              \
        _Pragma("unroll")                                                          \
        for (int s = 0; s < BN / 64; s++) {                                        \
            int c = tid + 256 * s;                                                 \
            int r = c >> 2, co = (c & 3) * 8;                                      \
            cp_async16(sB + (buf) * BN * 40 + r * 40 + co,                         \
                       Bw + (size_t)(n0 + r) * K + (k0) + co);                     \
        }                                                                          \
    }

    // prologue: tiles 0 and 1 (T >= 6 for all our shapes)
    LOAD_A(0, 0) LOAD_B(0, 0)
    cp_commit();
    LOAD_A(1, 32) LOAD_B(1, 32)
    cp_commit();

    for (int it = 0; it < T; it++) {
        cp_wait1();
        __syncthreads();
        if (it + 2 < T) {
            int nb = (it + 2) % 3;
            int k0 = (it + 2) << 5;
            LOAD_A(nb, k0)
            LOAD_B(nb, k0)
        }
        cp_commit();   // always commit (keeps wait-group indexing aligned)
        int buf = it % 3;
        const __nv_bfloat16* Ab = sA + buf * 128 * 40;
        const __nv_bfloat16* Bb = sB + buf * BN * 40;
#pragma unroll
        for (int kk = 0; kk < 2; kk++) {
            wmma::fragment<wmma::matrix_a, 16, 16, 16, __nv_bfloat16, wmma::row_major> af[2];
            wmma::fragment<wmma::matrix_b, 16, 16, 16, __nv_bfloat16, wmma::col_major> bfm[NF];
#pragma unroll
            for (int i = 0; i < 2; i++)
                wmma::load_matrix_sync(af[i], Ab + (wm + 16 * i) * 40 + kk * 16, 40);
#pragma unroll
            for (int j = 0; j < NF; j++)
                wmma::load_matrix_sync(bfm[j], Bb + (wn + 16 * j) * 40 + kk * 16, 40);
#pragma unroll
            for (int i = 0; i < 2; i++)
#pragma unroll
                for (int j = 0; j < NF; j++)
                    wmma::mma_sync(acc[i][j], af[i], bfm[j], acc[i][j]);
        }
    }
#undef LOAD_A
#undef LOAD_B
    __syncthreads();

    if (EPI == 0) {
#pragma unroll
        for (int i = 0; i < 2; i++)
#pragma unroll
            for (int j = 0; j < NF; j++)
                wmma::store_matrix_sync(&Cf[(size_t)(m0 + wm + 16 * i) * N + n0 + wn + 16 * j],
                                        acc[i][j], N, wmma::mem_row_major);
    } else if (EPI == 1 || EPI == 4) {
        constexpr int PAD = BN + 4;
        float* stage = (float*)smraw;
#pragma unroll
        for (int i = 0; i < 2; i++)
#pragma unroll
            for (int j = 0; j < NF; j++)
                wmma::store_matrix_sync(&stage[(wm + 16 * i) * PAD + wn + 16 * j],
                                        acc[i][j], PAD, wmma::mem_row_major);
        __syncthreads();
        constexpr int V = BN / 4;
        for (int idx = tid; idx < 128 * V; idx += 256) {
            int row = idx / V;
            int col = (idx % V) * 4;
            float4 v = *(const float4*)&stage[row * PAD + col];
            float r[4] = {v.x, v.y, v.z, v.w};
            if (EPI == 1) {
                float4 bo = *(const float4*)&bias[n0 + col];
                r[0] += bo.x; r[1] += bo.y; r[2] += bo.z; r[3] += bo.w;
#pragma unroll
                for (int q = 0; q < 4; q++)
                    r[q] = 0.5f * r[q] * (1.f + erff(r[q] * 0.70710678118654752f));
            }
            size_t off = (size_t)(m0 + row) * N + n0 + col;
            *(__nv_bfloat162*)&Cbf[off]     = __floats2bfloat162_rn(r[0], r[1]);
            *(__nv_bfloat162*)&Cbf[off + 2] = __floats2bfloat162_rn(r[2], r[3]);
        }
    } else {
        // EPI 2/3: transposed write to NCHW with residual (+bias for EPI 3)
        constexpr int PAD = BN + 4;
        float* stage = (float*)smraw;
#pragma unroll
        for (int i = 0; i < 2; i++)
#pragma unroll
            for (int j = 0; j < NF; j++)
                wmma::store_matrix_sync(&stage[(wm + 16 * i) * PAD + wn + 16 * j],
                                        acc[i][j], PAD, wmma::mem_row_major);
        __syncthreads();
        int lane = tid & 31;
        for (int col = wid; col < BN; col += 8) {
            int c = n0 + col;
            float badd = (EPI == 3) ? bias[c] : 0.f;
#pragma unroll
            for (int rg = 0; rg < 4; rg++) {
                int row = rg * 32 + lane;
                int m = m0 + row;
                int b = m / HWX, l = m - b * HWX;
                size_t idx = ((size_t)b * CC + c) * HWX + l;
                Cf[idx] = resid[idx] + stage[row * PAD + col] + badd;
            }
        }
    }
}

// ---------------- causal depthwise conv1d (k=3) + SiLU, bf16 in/out ------------
__global__ void k_conv1d(const float* __restrict__ cb) {
    int idx = blockIdx.x * 256 + threadIdx.x;
    if (idx >= LTOK * (DIN / 4)) return;
    int q = idx % (DIN / 4);
    int d = q * 4;
    size_t row = idx / (DIN / 4);
    int l = (int)(row % HWX);
    float4 w0 = *(const float4*)&g_cw_t[0 * DIN + d];
    float4 w1 = *(const float4*)&g_cw_t[1 * DIN + d];
    float4 w2 = *(const float4*)&g_cw_t[2 * DIN + d];
    float4 b4 = *(const float4*)&cb[d];
    const __nv_bfloat16* base = g_xz + row * 2 * DIN + d;
    float4 v2 = ld_bf4(base);
    float4 v1 = make_float4(0.f, 0.f, 0.f, 0.f);
    float4 v0 = make_float4(0.f, 0.f, 0.f, 0.f);
    if (l >= 1) v1 = ld_bf4(base - 2 * DIN);
    if (l >= 2) v0 = ld_bf4(base - 4 * DIN);
    float a0 = b4.x + w0.x * v0.x + w1.x * v1.x + w2.x * v2.x;
    float a1 = b4.y + w0.y * v0.y + w1.y * v1.y + w2.y * v2.y;
    float a2 = b4.z + w0.z * v0.z + w1.z * v1.z + w2.z * v2.z;
    float a3 = b4.w + w0.w * v0.w + w1.w * v1.w + w2.w * v2.w;
    a0 = a0 / (1.f + __expf(-a0));
    a1 = a1 / (1.f + __expf(-a1));
    a2 = a2 / (1.f + __expf(-a2));
    a3 = a3 / (1.f + __expf(-a3));
    size_t off = row * DIN + d;
    *(__nv_bfloat162*)&g_xmc_bf[off]     = __floats2bfloat162_rn(a0, a1);
    *(__nv_bfloat162*)&g_xmc_bf[off + 2] = __floats2bfloat162_rn(a2, a3);
}

// ---------------- softplus helper ----------------------------------------------
__device__ __forceinline__ float softplusf(float s) {
    return (s > 15.f) ? s : log1pf(__expf(s));
}

// ---------------- chunked selective scan (dt_proj fused) ------------------------
// thread = (b, d, chunk); 16 n-states in registers, dt/B/C staged in smem.
__global__ void k_scanA2(const float* __restrict__ A_log,
                         const float* __restrict__ dtw, const float* __restrict__ dtb) {
    int blk = blockIdx.x;                 // ((b*NCH + ch)*3 + ds)
    int ds = blk % 3;
    int t0 = blk / 3;
    int ch = t0 % NCH, b = t0 / NCH;
    int tid = threadIdx.x;                // 128
    int d = ds * 128 + tid;
    __shared__ float sDt[CL][DTR];
    __shared__ float sB[CL][DST];
    size_t tb = (size_t)b * HWX + (size_t)ch * CL;
    for (int e = tid; e < CL * 28; e += 128) {
        int t = e / 28, c = e % 28;
        float v = g_xdbl[(tb + t) * 64 + c];
        if (c < DTR) sDt[t][c] = v;
        else         sB[t][c - DTR] = v;
    }
    __syncthreads();
    float wdt[DTR];
#pragma unroll
    for (int k = 0; k < DTR; k++) wdt[k] = __ldg(&dtw[d * DTR + k]);
    float db = __ldg(&dtb[d]);
    float An[DST], P[DST], S[DST];
#pragma unroll
    for (int n = 0; n < DST; n++) {
        An[n] = -expf(A_log[d * DST + n]);
        P[n] = 1.f; S[n] = 0.f;
    }
    const __nv_bfloat16* px = g_xmc_bf + tb * DIN + d;
    for (int t = 0; t < CL; t++) {
        float s = db;
#pragma unroll
        for (int k = 0; k < DTR; k++) s = fmaf(wdt[k], sDt[t][k], s);
        float del = softplusf(s);
        float xv  = __bfloat162float(px[(size_t)t * DIN]);
        float u = del * xv;
#pragma unroll
        for (int n = 0; n < DST; n++) {
            float dA = __expf(del * An[n]);
            P[n] *= dA;
            S[n] = fmaf(dA, S[n], u * sB[t][n]);
        }
    }
    size_t bse = ((size_t)(b * NCH + ch) * DST) * DIN + d;
#pragma unroll
    for (int n = 0; n < DST; n++) {
        g_cP[bse + (size_t)n * DIN] = P[n];
        g_cS[bse + (size_t)n * DIN] = S[n];
    }
}

__global__ void k_scanB2() {
    int i = blockIdx.x * 256 + threadIdx.x;   // < BB*DST*DIN
    if (i >= BB * DST * DIN) return;
    int d = i % DIN;
    int n = (i / DIN) % DST;
    int b = i / (DIN * DST);
    float h = 0.f;
    for (int ch = 0; ch < NCH; ch++) {
        size_t idx = ((size_t)(b * NCH + ch) * DST + n) * DIN + d;
        g_h0[idx] = h;
        h = fmaf(g_cP[idx], h, g_cS[idx]);
    }
}

__global__ void k_scanC2(const float* __restrict__ A_log, const float* __restrict__ Dskip,
                         const float* __restrict__ dtw, const float* __restrict__ dtb) {
    int blk = blockIdx.x;
    int ds = blk % 3;
    int t0 = blk / 3;
    int ch = t0 % NCH, b = t0 / NCH;
    int tid = threadIdx.x;
    int d = ds * 128 + tid;
    __shared__ float sDt[CL][DTR];
    __shared__ float2 sBC[CL][DST];
    size_t tb = (size_t)b * HWX + (size_t)ch * CL;
    for (int e = tid; e < CL * 28; e += 128) {
        int t = e / 28, c = e % 28;
        if (c < DTR) sDt[t][c] = g_xdbl[(tb + t) * 64 + c];
        else {
            int n = c - DTR;
            sBC[t][n] = make_float2(g_xdbl[(tb + t) * 64 + 12 + n],
                                    g_xdbl[(tb + t) * 64 + 28 + n]);
        }
    }
    __syncthreads();
    float wdt[DTR];
#pragma unroll
    for (int k = 0; k < DTR; k++) wdt[k] = __ldg(&dtw[d * DTR + k]);
    float db = __ldg(&dtb[d]);
    float An[DST], h[DST];
    size_t bse = ((size_t)(b * NCH + ch) * DST) * DIN + d;
#pragma unroll
    for (int n = 0; n < DST; n++) {
        An[n] = -expf(A_log[d * DST + n]);
        h[n] = g_h0[bse + (size_t)n * DIN];
    }
    float Dsk = Dskip[d];
    const __nv_bfloat16* px = g_xmc_bf + tb * DIN + d;
    const __nv_bfloat16* pz = g_xz     + tb * 2 * DIN + DIN + d;
    __nv_bfloat16*       py = g_ybf    + tb * DIN + d;
    for (int t = 0; t < CL; t++) {
        float s = db;
#pragma unroll
        for (int k = 0; k < DTR; k++) s = fmaf(wdt[k], sDt[t][k], s);
        float del = softplusf(s);
        float xv  = __bfloat162float(px[(size_t)t * DIN]);
        float zv  = __bfloat162float(pz[(size_t)t * 2 * DIN]);
        float u = del * xv;
        float y = 0.f;
#pragma unroll
        for (int n = 0; n < DST; n++) {
            float dA = __expf(del * An[n]);
            h[n] = fmaf(dA, h[n], u * sBC[t][n].x);
            y = fmaf(h[n], sBC[t][n].y, y);
        }
        float sz = zv / (1.f + __expf(-zv));
        py[(size_t)t * DIN] = __float2bfloat16((y + xv * Dsk) * sz);
    }
}

// ---------------- dw 3x3 conv + BN + exact GELU + residual (smem tiled) -------
__global__ void k_dw(const float* __restrict__ w, const float* __restrict__ bg,
                     const float* __restrict__ bb, const float* __restrict__ bm,
                     const float* __restrict__ bv) {
    __shared__ float t[16][58];
    int strip = blockIdx.x;          // 0..3, 14 rows each
    int c = blockIdx.y;
    int b = blockIdx.z;
    int tid = threadIdx.x;
    const float* plane = g_x1 + ((size_t)b * CC + c) * HWX;

    for (int i = tid; i < 16 * 58; i += 256) {
        int r = i / 58, cc = i % 58;
        int hy = strip * 14 - 1 + r;
        int wx = cc - 1;
        t[r][cc] = (hy >= 0 && hy < HH && wx >= 0 && wx < WWD) ? plane[hy * WWD + wx] : 0.f;
    }
    __syncthreads();

    float w9[9];
#pragma unroll
    for (int k = 0; k < 9; k++) w9[k] = __ldg(&w[c * 9 + k]);
    float mean = bm[c], g = bg[c], beta = bb[c];
    float rs = rsqrtf(bv[c] + 1e-5f);

    float* outp = g_x2 + ((size_t)b * CC + c) * HWX;
    for (int i = tid; i < 14 * WWD; i += 256) {
        int r = i / WWD, wc = i % WWD;
        float acc = 0.f;
#pragma unroll
        for (int ky = 0; ky < 3; ky++)
#pragma unroll
            for (int kx = 0; kx < 3; kx++)
                acc = fmaf(t[r + ky][wc + kx], w9[ky * 3 + kx], acc);
        float bn = (acc - mean) * rs * g + beta;
        float gl = 0.5f * bn * (1.f + erff(bn * 0.70710678118654752f));
        outp[(strip * 14 + r) * WWD + wc] = t[r + 1][wc + 1] + gl;
    }
}

// ---------------------------------------------------------------------------
extern "C" void kernel_launch(void* const* d_in, const int* in_sizes, int n_in,
                              void* d_out, int out_size) {
    const float* x         = (const float*)d_in[0];
    const float* ln1_g     = (const float*)d_in[1];
    const float* ln1_b     = (const float*)d_in[2];
    const float* in_proj_w = (const float*)d_in[3];
    const float* conv1d_w  = (const float*)d_in[4];
    const float* conv1d_b  = (const float*)d_in[5];
    const float* x_proj_w  = (const float*)d_in[6];
    const float* dt_proj_w = (const float*)d_in[7];
    const float* dt_proj_b = (const float*)d_in[8];
    const float* A_log     = (const float*)d_in[9];
    const float* Dskip     = (const float*)d_in[10];
    const float* out_proj_w= (const float*)d_in[11];
    const float* dw_w      = (const float*)d_in[12];
    const float* bn_g      = (const float*)d_in[13];
    const float* bn_b      = (const float*)d_in[14];
    const float* bn_mean   = (const float*)d_in[15];
    const float* bn_var    = (const float*)d_in[16];
    const float* ln2_g     = (const float*)d_in[17];
    const float* ln2_b     = (const float*)d_in[18];
    const float* mlp_w1    = (const float*)d_in[19];
    const float* mlp_b1    = (const float*)d_in[20];
    const float* mlp_w2    = (const float*)d_in[21];
    const float* mlp_b2    = (const float*)d_in[22];
    float* out = (float*)d_out;

    float *p_xdbl, *p_x1, *p_x2;
    __nv_bfloat16 *p_tokb, *p_xz, *p_xmcb, *p_xwb, *p_win, *p_wout, *p_w1, *p_w2,
                  *p_ybf, *p_tok2b, *p_hidb;
    cudaGetSymbolAddress((void**)&p_xdbl,  g_xdbl);
    cudaGetSymbolAddress((void**)&p_x1,    g_x1);
    cudaGetSymbolAddress((void**)&p_x2,    g_x2);
    cudaGetSymbolAddress((void**)&p_tokb,  g_tok_bf);
    cudaGetSymbolAddress((void**)&p_xz,    g_xz);
    cudaGetSymbolAddress((void**)&p_xmcb,  g_xmc_bf);
    cudaGetSymbolAddress((void**)&p_xwb,   g_xw_bf);
    cudaGetSymbolAddress((void**)&p_win,   g_w_in);
    cudaGetSymbolAddress((void**)&p_wout,  g_w_out);
    cudaGetSymbolAddress((void**)&p_w1,    g_w1);
    cudaGetSymbolAddress((void**)&p_w2,    g_w2);
    cudaGetSymbolAddress((void**)&p_ybf,   g_ybf);
    cudaGetSymbolAddress((void**)&p_tok2b, g_tok2_bf);
    cudaGetSymbolAddress((void**)&p_hidb,  g_hid_bf);

    // dynamic smem sizes (3-stage pipe vs epilogue stage, whichever larger)
    const int SM128 = 128 * 132 * 4;                           // 67584 >= 61440 pipe
    const int SM64  = (3 * 128 * 40 + 3 * 64 * 40) * 2;        // 46080 >= 34816 stage
    cudaFuncSetAttribute(k_gemmbf<128, 4>, cudaFuncAttributeMaxDynamicSharedMemorySize, SM128);
    cudaFuncSetAttribute(k_gemmbf<128, 1>, cudaFuncAttributeMaxDynamicSharedMemorySize, SM128);
    cudaFuncSetAttribute(k_gemmbf<64,  0>, cudaFuncAttributeMaxDynamicSharedMemorySize, SM64);
    cudaFuncSetAttribute(k_gemmbf<64,  2>, cudaFuncAttributeMaxDynamicSharedMemorySize, SM64);
    cudaFuncSetAttribute(k_gemmbf<64,  3>, cudaFuncAttributeMaxDynamicSharedMemorySize, SM64);

    dim3 lnGrid(HWX / 32, BB);
    const int CVTN = 2 * DIN * CC + CC * DIN + 4 * CC * CC + CC * 4 * CC + 3 * DIN + 64 * DIN;

    // 0: weight prep
    k_cvtw<<<(CVTN + 255) / 256, 256>>>(in_proj_w, out_proj_w, mlp_w1, mlp_w2, conv1d_w, x_proj_w);
    // 1: LN1 -> bf16 tokens
    k_ln<<<lnGrid, 256>>>(x, ln1_g, ln1_b, p_tokb);
    // 2: in_proj (M,192)->(M,768) bf16 out
    k_gemmbf<128, 4><<<dim3(LTOK / 128, 6), 256, SM128>>>(p_tokb, p_win, nullptr, nullptr, nullptr, p_xz, 2 * DIN, CC);
    // 3: conv1d + silu (bf16 in/out)
    k_conv1d<<<(LTOK * (DIN / 4) + 255) / 256, 256>>>(conv1d_b);
    // 4: x_proj padded GEMM (M,384)->(M,64) fp32 out
    k_gemmbf<64, 0><<<dim3(LTOK / 128, 1), 256, SM64>>>(p_xmcb, p_xwb, nullptr, nullptr, p_xdbl, nullptr, 64, DIN);
    // 5-7: chunked selective scan (dt_proj fused)
    k_scanA2<<<BB * NCH * 3, 128>>>(A_log, dt_proj_w, dt_proj_b);
    k_scanB2<<<(BB * DST * DIN + 255) / 256, 256>>>();
    k_scanC2<<<BB * NCH * 3, 128>>>(A_log, Dskip, dt_proj_w, dt_proj_b);
    // 8: out_proj + fused transpose + residual -> x1 (NCHW)
    k_gemmbf<64, 2><<<dim3(LTOK / 128, 3), 256, SM64>>>(p_ybf, p_wout, nullptr, x, p_x1, nullptr, CC, DIN);
    // 9: dw conv + BN + gelu + residual -> x2
    k_dw<<<dim3(4, CC, BB), 256>>>(dw_w, bn_g, bn_b, bn_mean, bn_var);
    // 10: LN2 -> bf16 tokens
    k_ln<<<lnGrid, 256>>>(p_x2, ln2_g, ln2_b, p_tok2b);
    // 11: mlp1 + fused bias + gelu -> bf16 hidden
    k_gemmbf<128, 1><<<dim3(LTOK / 128, 6), 256, SM128>>>(p_tok2b, p_w1, mlp_b1, nullptr, nullptr, p_hidb, 4 * CC, CC);
    // 12: mlp2 + fused transpose + residual + bias -> out (NCHW)
    k_gemmbf<64, 3><<<dim3(LTOK / 128, 3), 256, SM64>>>(p_hidb, p_w2, mlp_b2, p_x2, out, nullptr, CC, 4 * CC);
}